// round 1
// baseline (speedup 1.0000x reference)
#include <cuda_runtime.h>

#define BB 8
#define CC 256
#define CPD 32
#define NND 4096
#define TP 132   // smem tile pitch (conflict-free-ish, float4-aligned)

// ---------------- scratch (__device__ globals; no allocs allowed) ----------------
__device__ float g_q[(size_t)BB * NND * CPD];   // [b][n][cp]  4 MB
__device__ float g_k[(size_t)BB * NND * CPD];
__device__ float g_v[(size_t)BB * NND * CPD];
__device__ float g_A[BB * NND];                 // row max of S (per j)
__device__ float g_iZ[BB * NND];                // 1 / row sum of exp(S - A)

// ---------------- kernel 1: 1x1-conv projection (q/k/v) ----------------
// grid (N/128, B), block 128. out layout [b][n][cp].
__global__ __launch_bounds__(128) void proj_kernel(
    const float* __restrict__ x, const float* __restrict__ W,
    const float* __restrict__ bias, float* __restrict__ out)
{
    __shared__ float Ws[CC * CPD];   // [c][o], 32 KB
    const int tid = threadIdx.x;
    const int b = blockIdx.y;
    const int n = blockIdx.x * 128 + tid;

    for (int idx = tid; idx < CC * CPD; idx += 128)
        Ws[idx] = W[(idx & 31) * CC + (idx >> 5)];
    __syncthreads();

    float acc[CPD];
#pragma unroll
    for (int o = 0; o < CPD; o++) acc[o] = bias[o];

    const float* xp = x + (size_t)b * CC * NND + n;
#pragma unroll 4
    for (int c = 0; c < CC; c++) {
        float xv = __ldg(xp + (size_t)c * NND);
        const float4* w4 = (const float4*)(Ws + c * CPD);
#pragma unroll
        for (int oq = 0; oq < CPD / 4; oq++) {
            float4 w = w4[oq];
            acc[oq * 4 + 0] += w.x * xv;
            acc[oq * 4 + 1] += w.y * xv;
            acc[oq * 4 + 2] += w.z * xv;
            acc[oq * 4 + 3] += w.w * xv;
        }
    }
    float* op = out + ((size_t)b * NND + n) * CPD;
#pragma unroll
    for (int oq = 0; oq < CPD / 4; oq++)
        ((float4*)op)[oq] = make_float4(acc[oq * 4 + 0], acc[oq * 4 + 1],
                                        acc[oq * 4 + 2], acc[oq * 4 + 3]);
}

// ---------------- kernel 2: pass 1 — per-row (A, 1/Z) of softmax(Q^T K) ----------------
// grid (N/128 j-tiles, B), block 256. Thread (tjg,tig) owns 8 j-rows x 8 i-cols.
__global__ __launch_bounds__(256) void pass1_kernel()
{
    __shared__ float sm[2 * 32 * TP];   // qs | ks (kk-major), ~33 KB
    float* qs = sm;
    float* ks = sm + 32 * TP;

    const int tid = threadIdx.x;
    const int b = blockIdx.y;
    const int j0 = blockIdx.x * 128;
    const int tjg = tid >> 4, tig = tid & 15;

    for (int idx = tid; idx < 4096; idx += 256) {
        int j = idx >> 5, kk = idx & 31;
        qs[kk * TP + j] = g_q[((size_t)(b * NND + j0 + j)) * CPD + kk];
    }

    float m[8], z[8];
#pragma unroll
    for (int r = 0; r < 8; r++) { m[r] = -1e30f; z[r] = 0.f; }

    for (int it = 0; it < NND / 128; it++) {
        __syncthreads();
        const int i0 = it * 128;
        for (int idx = tid; idx < 4096; idx += 256) {
            int i = idx >> 5, kk = idx & 31;
            ks[kk * TP + i] = g_k[((size_t)(b * NND + i0 + i)) * CPD + kk];
        }
        __syncthreads();

        float sacc[8][8];
#pragma unroll
        for (int r = 0; r < 8; r++)
#pragma unroll
            for (int c = 0; c < 8; c++) sacc[r][c] = 0.f;

#pragma unroll 8
        for (int kk = 0; kk < 32; kk++) {
            float4 a0 = *(const float4*)&qs[kk * TP + tjg * 8];
            float4 a1 = *(const float4*)&qs[kk * TP + tjg * 8 + 4];
            float4 b0 = *(const float4*)&ks[kk * TP + tig * 8];
            float4 b1 = *(const float4*)&ks[kk * TP + tig * 8 + 4];
            float aj[8] = {a0.x, a0.y, a0.z, a0.w, a1.x, a1.y, a1.z, a1.w};
            float bi[8] = {b0.x, b0.y, b0.z, b0.w, b1.x, b1.y, b1.z, b1.w};
#pragma unroll
            for (int r = 0; r < 8; r++)
#pragma unroll
                for (int c = 0; c < 8; c++)
                    sacc[r][c] += aj[r] * bi[c];
        }

#pragma unroll
        for (int r = 0; r < 8; r++) {
            float tm = sacc[r][0];
#pragma unroll
            for (int c = 1; c < 8; c++) tm = fmaxf(tm, sacc[r][c]);
            float mn = fmaxf(m[r], tm);
            float corr = __expf(m[r] - mn);
            float s = 0.f;
#pragma unroll
            for (int c = 0; c < 8; c++) s += __expf(sacc[r][c] - mn);
            z[r] = z[r] * corr + s;
            m[r] = mn;
        }
    }

    // cross-thread (tig) reduction per j-row, staged in the ks region
    __syncthreads();
    float* rm = ks;
    float* rz = ks + 2048;
#pragma unroll
    for (int r = 0; r < 8; r++) {
        int j = tjg * 8 + r;
        rm[j * 16 + tig] = m[r];
        rz[j * 16 + tig] = z[r];
    }
    __syncthreads();
    if (tid < 128) {
        int j = tid;
        float M = -1e30f;
#pragma unroll
        for (int t = 0; t < 16; t++) M = fmaxf(M, rm[j * 16 + t]);
        float Z = 0.f;
#pragma unroll
        for (int t = 0; t < 16; t++) Z += rz[j * 16 + t] * __expf(rm[j * 16 + t] - M);
        g_A[b * NND + j0 + j] = M;
        g_iZ[b * NND + j0 + j] = 1.0f / Z;
    }
}

// ---------------- kernel 3: pass 2 — fused attention + back-proj + residual ----------------
// grid (N/128 i-tiles, B), block 256, dynamic smem.
#define S2_KST 0
#define S2_QST (32 * TP)                 // 4224
#define S2_VS  (2 * 32 * TP)             // 8448
#define S2_AS  (S2_VS + 128 * 32)        // 12544
#define S2_P   (S2_AS + 128)             // 12672
#define S2_WB  (S2_P + 128 * 128)        // 29056
#define S2_BB  (S2_WB + 256 * 32)        // 37248
#define S2_TOT (S2_BB + 256)             // 37504 floats = 150016 B

__global__ __launch_bounds__(256, 1) void pass2_kernel(
    const float* __restrict__ x, const float* __restrict__ Wb,
    const float* __restrict__ bbp, float* __restrict__ y)
{
    extern __shared__ float sm[];
    float* ksT = sm + S2_KST;
    float* qsT = sm + S2_QST;
    float* vs  = sm + S2_VS;
    float* As  = sm + S2_AS;
    float* P   = sm + S2_P;
    float* Wbs = sm + S2_WB;
    float* bbs = sm + S2_BB;

    const int tid = threadIdx.x;
    const int b = blockIdx.y;
    const int i0 = blockIdx.x * 128;
    const int tjg = tid >> 4, tig = tid & 15;   // s-gemm mapping
    const int ci = tid >> 5, ii = tid & 31;     // p-gemm mapping

    // stationary: K columns for this i-tile, Wb, bb
    for (int idx = tid; idx < 4096; idx += 256) {
        int i = idx >> 5, kk = idx & 31;
        ksT[kk * TP + i] = g_k[((size_t)(b * NND + i0 + i)) * CPD + kk];
    }
    for (int idx = tid; idx < 256 * 32; idx += 256) Wbs[idx] = Wb[idx];
    if (tid < 256) bbs[tid] = bbp[tid];

    float oacc[4][4];
#pragma unroll
    for (int a = 0; a < 4; a++)
#pragma unroll
        for (int e = 0; e < 4; e++) oacc[a][e] = 0.f;

    for (int jt = 0; jt < NND / 128; jt++) {
        __syncthreads();   // previous p-gemm done (vs/qsT free); also covers stationary loads
        const int j0 = jt * 128;
        for (int idx = tid; idx < 4096; idx += 256) {
            int j = idx >> 5, kk = idx & 31;
            qsT[kk * TP + j] = g_q[((size_t)(b * NND + j0 + j)) * CPD + kk];
        }
        for (int idx = tid; idx < 4096; idx += 256) {
            int j = idx >> 5, c = idx & 31;
            int gj = b * NND + j0 + j;
            vs[idx] = g_v[(size_t)gj * CPD + c] * g_iZ[gj];  // fold 1/Z into V
        }
        if (tid < 128) As[tid] = g_A[b * NND + j0 + tid];
        __syncthreads();

        // s-gemm: sacc[j-frag][i-frag]
        float sacc[8][8];
#pragma unroll
        for (int r = 0; r < 8; r++)
#pragma unroll
            for (int c = 0; c < 8; c++) sacc[r][c] = 0.f;

#pragma unroll 8
        for (int kk = 0; kk < 32; kk++) {
            float4 a0 = *(const float4*)&qsT[kk * TP + tjg * 8];
            float4 a1 = *(const float4*)&qsT[kk * TP + tjg * 8 + 4];
            float4 b0 = *(const float4*)&ksT[kk * TP + tig * 8];
            float4 b1 = *(const float4*)&ksT[kk * TP + tig * 8 + 4];
            float aj[8] = {a0.x, a0.y, a0.z, a0.w, a1.x, a1.y, a1.z, a1.w};
            float bi[8] = {b0.x, b0.y, b0.z, b0.w, b1.x, b1.y, b1.z, b1.w};
#pragma unroll
            for (int r = 0; r < 8; r++)
#pragma unroll
                for (int c = 0; c < 8; c++)
                    sacc[r][c] += aj[r] * bi[c];
        }

        // P = exp(s - A_j)  (1/Z already folded into vs)
#pragma unroll
        for (int r = 0; r < 8; r++) {
            float a = As[tjg * 8 + r];
            float4 p0, p1;
            p0.x = __expf(sacc[r][0] - a);
            p0.y = __expf(sacc[r][1] - a);
            p0.z = __expf(sacc[r][2] - a);
            p0.w = __expf(sacc[r][3] - a);
            p1.x = __expf(sacc[r][4] - a);
            p1.y = __expf(sacc[r][5] - a);
            p1.z = __expf(sacc[r][6] - a);
            p1.w = __expf(sacc[r][7] - a);
            *(float4*)&P[(tjg * 8 + r) * 128 + tig * 8]     = p0;
            *(float4*)&P[(tjg * 8 + r) * 128 + tig * 8 + 4] = p1;
        }
        __syncthreads();

        // p-gemm: oacc[c-frag][i-frag] += P[j][i] * vs[j][c]
#pragma unroll 2
        for (int j = 0; j < 128; j++) {
            float4 v4 = *(const float4*)&vs[j * 32 + ci * 4];
            float4 p4 = *(const float4*)&P[j * 128 + ii * 4];
            float vv[4] = {v4.x, v4.y, v4.z, v4.w};
            float pp[4] = {p4.x, p4.y, p4.z, p4.w};
#pragma unroll
            for (int a = 0; a < 4; a++)
#pragma unroll
                for (int e = 0; e < 4; e++)
                    oacc[a][e] += vv[a] * pp[e];
        }
    }

    // stage out tile [32 x 128] into P region
    __syncthreads();
#pragma unroll
    for (int a = 0; a < 4; a++)
        *(float4*)&P[(ci * 4 + a) * 128 + ii * 4] =
            make_float4(oacc[a][0], oacc[a][1], oacc[a][2], oacc[a][3]);
    __syncthreads();

    // epilogue: y[b][cf][i] = Wb @ out + bb + x
    const int i = tid & 127;
    const int half = tid >> 7;
    const size_t base = ((size_t)b * CC + half * 128) * NND + i0 + i;
    for (int cf0 = 0; cf0 < 128; cf0++) {
        const int cf = half * 128 + cf0;
        float acc = bbs[cf];
#pragma unroll
        for (int t = 0; t < 32; t += 4) {
            float4 w = *(const float4*)&Wbs[cf * 32 + t];
            acc += w.x * P[(t + 0) * 128 + i];
            acc += w.y * P[(t + 1) * 128 + i];
            acc += w.z * P[(t + 2) * 128 + i];
            acc += w.w * P[(t + 3) * 128 + i];
        }
        const size_t off = base + (size_t)cf0 * NND;
        y[off] = acc + x[off];
    }
}

// ---------------- launcher ----------------
extern "C" void kernel_launch(void* const* d_in, const int* in_sizes, int n_in,
                              void* d_out, int out_size)
{
    const float* x   = (const float*)d_in[0];
    const float* Wq  = (const float*)d_in[1];
    const float* bq  = (const float*)d_in[2];
    const float* Wk  = (const float*)d_in[3];
    const float* bk  = (const float*)d_in[4];
    const float* Wv  = (const float*)d_in[5];
    const float* bv  = (const float*)d_in[6];
    const float* Wb  = (const float*)d_in[7];
    const float* bbp = (const float*)d_in[8];
    float* y = (float*)d_out;

    float *dq, *dk, *dv;
    cudaGetSymbolAddress((void**)&dq, g_q);
    cudaGetSymbolAddress((void**)&dk, g_k);
    cudaGetSymbolAddress((void**)&dv, g_v);

    cudaFuncSetAttribute(pass2_kernel, cudaFuncAttributeMaxDynamicSharedMemorySize,
                         S2_TOT * (int)sizeof(float));

    dim3 gp(NND / 128, BB);
    proj_kernel<<<gp, 128>>>(x, Wq, bq, dq);
    proj_kernel<<<gp, 128>>>(x, Wk, bk, dk);
    proj_kernel<<<gp, 128>>>(x, Wv, bv, dv);
    pass1_kernel<<<dim3(NND / 128, BB), 256>>>();
    pass2_kernel<<<dim3(NND / 128, BB), 256, S2_TOT * sizeof(float)>>>(x, Wb, bbp, y);
}

// round 2
// speedup vs baseline: 1.0149x; 1.0149x over previous
#include <cuda_runtime.h>

#define BB 8
#define CC 256
#define CPD 32
#define NND 4096
#define TP 132   // smem tile pitch (conflict-free-ish, float4-aligned)

typedef unsigned long long u64;

// ---- packed f32x2 helpers (sm_100+) ----
__device__ __forceinline__ u64 pack2(float lo, float hi) {
    u64 r; asm("mov.b64 %0,{%1,%2};" : "=l"(r) : "f"(lo), "f"(hi)); return r;
}
__device__ __forceinline__ u64 fma2(u64 a, u64 b, u64 c) {
    u64 d; asm("fma.rn.f32x2 %0,%1,%2,%3;" : "=l"(d) : "l"(a), "l"(b), "l"(c)); return d;
}
__device__ __forceinline__ void unpack2(u64 v, float& lo, float& hi) {
    asm("mov.b64 {%0,%1},%2;" : "=f"(lo), "=f"(hi) : "l"(v));
}

// ---------------- scratch (__device__ globals; no allocs allowed) ----------------
__device__ float g_q[(size_t)BB * NND * CPD];   // [b][n][cp]  4 MB
__device__ float g_k[(size_t)BB * NND * CPD];
__device__ float g_v[(size_t)BB * NND * CPD];
__device__ float g_A[BB * NND];                 // row max of S (per j)
__device__ float g_iZ[BB * NND];                // 1 / row sum of exp(S - A)

// ---------------- kernel 1: 1x1-conv projection (q/k/v) ----------------
// grid (N/128, B), block 128. out layout [b][n][cp].
__global__ __launch_bounds__(128) void proj_kernel(
    const float* __restrict__ x, const float* __restrict__ W,
    const float* __restrict__ bias, float* __restrict__ out)
{
    __shared__ float Ws[CC * CPD];   // [c][o], 32 KB
    const int tid = threadIdx.x;
    const int b = blockIdx.y;
    const int n = blockIdx.x * 128 + tid;

    for (int idx = tid; idx < CC * CPD; idx += 128)
        Ws[idx] = W[(idx & 31) * CC + (idx >> 5)];
    __syncthreads();

    u64 acc2[CPD / 2];
#pragma unroll
    for (int o2 = 0; o2 < CPD / 2; o2++)
        acc2[o2] = pack2(bias[o2 * 2], bias[o2 * 2 + 1]);

    const float* xp = x + (size_t)b * CC * NND + n;
#pragma unroll 4
    for (int c = 0; c < CC; c++) {
        float xv = __ldg(xp + (size_t)c * NND);
        u64 xv2 = pack2(xv, xv);
        const ulonglong2* w2 = (const ulonglong2*)(Ws + c * CPD);
#pragma unroll
        for (int oq = 0; oq < CPD / 4; oq++) {
            ulonglong2 w = w2[oq];
            acc2[oq * 2 + 0] = fma2(xv2, w.x, acc2[oq * 2 + 0]);
            acc2[oq * 2 + 1] = fma2(xv2, w.y, acc2[oq * 2 + 1]);
        }
    }
    ulonglong2* op = (ulonglong2*)(out + ((size_t)b * NND + n) * CPD);
#pragma unroll
    for (int oq = 0; oq < CPD / 4; oq++) {
        ulonglong2 w; w.x = acc2[oq * 2]; w.y = acc2[oq * 2 + 1];
        op[oq] = w;
    }
}

// ---------------- kernel 2: pass 1 — per-row (A, 1/Z) of softmax(Q^T K) ----------------
// grid (N/128 j-tiles, B), block 256. Thread (tjg,tig) owns 8 j-rows x 8 i-cols.
__global__ __launch_bounds__(256) void pass1_kernel()
{
    __shared__ float sm[2 * 32 * TP];   // qs | ks (kk-major), ~33 KB
    float* qs = sm;
    float* ks = sm + 32 * TP;

    const int tid = threadIdx.x;
    const int b = blockIdx.y;
    const int j0 = blockIdx.x * 128;
    const int tjg = tid >> 4, tig = tid & 15;

    for (int idx = tid; idx < 4096; idx += 256) {
        int j = idx >> 5, kk = idx & 31;
        qs[kk * TP + j] = g_q[((size_t)(b * NND + j0 + j)) * CPD + kk];
    }

    float m[8], z[8];
#pragma unroll
    for (int r = 0; r < 8; r++) { m[r] = -1e30f; z[r] = 0.f; }

    for (int it = 0; it < NND / 128; it++) {
        __syncthreads();
        const int i0 = it * 128;
        for (int idx = tid; idx < 4096; idx += 256) {
            int i = idx >> 5, kk = idx & 31;
            ks[kk * TP + i] = g_k[((size_t)(b * NND + i0 + i)) * CPD + kk];
        }
        __syncthreads();

        u64 sacc2[8][4];
#pragma unroll
        for (int r = 0; r < 8; r++)
#pragma unroll
            for (int c2 = 0; c2 < 4; c2++) sacc2[r][c2] = 0ULL;

#pragma unroll 8
        for (int kk = 0; kk < 32; kk++) {
            float4 a0 = *(const float4*)&qs[kk * TP + tjg * 8];
            float4 a1 = *(const float4*)&qs[kk * TP + tjg * 8 + 4];
            ulonglong2 bb0 = *(const ulonglong2*)&ks[kk * TP + tig * 8];
            ulonglong2 bb1 = *(const ulonglong2*)&ks[kk * TP + tig * 8 + 4];
            u64 bi2[4] = {bb0.x, bb0.y, bb1.x, bb1.y};
            float aj[8] = {a0.x, a0.y, a0.z, a0.w, a1.x, a1.y, a1.z, a1.w};
#pragma unroll
            for (int r = 0; r < 8; r++) {
                u64 a2 = pack2(aj[r], aj[r]);
#pragma unroll
                for (int c2 = 0; c2 < 4; c2++)
                    sacc2[r][c2] = fma2(a2, bi2[c2], sacc2[r][c2]);
            }
        }

#pragma unroll
        for (int r = 0; r < 8; r++) {
            float sv[8];
#pragma unroll
            for (int c2 = 0; c2 < 4; c2++)
                unpack2(sacc2[r][c2], sv[c2 * 2], sv[c2 * 2 + 1]);
            float tm = sv[0];
#pragma unroll
            for (int c = 1; c < 8; c++) tm = fmaxf(tm, sv[c]);
            float mn = fmaxf(m[r], tm);
            float corr = __expf(m[r] - mn);
            float s = 0.f;
#pragma unroll
            for (int c = 0; c < 8; c++) s += __expf(sv[c] - mn);
            z[r] = z[r] * corr + s;
            m[r] = mn;
        }
    }

    // cross-thread (tig) reduction per j-row, staged in the ks region
    __syncthreads();
    float* rm = ks;
    float* rz = ks + 2048;
#pragma unroll
    for (int r = 0; r < 8; r++) {
        int j = tjg * 8 + r;
        rm[j * 16 + tig] = m[r];
        rz[j * 16 + tig] = z[r];
    }
    __syncthreads();
    if (tid < 128) {
        int j = tid;
        float M = -1e30f;
#pragma unroll
        for (int t = 0; t < 16; t++) M = fmaxf(M, rm[j * 16 + t]);
        float Z = 0.f;
#pragma unroll
        for (int t = 0; t < 16; t++) Z += rz[j * 16 + t] * __expf(rm[j * 16 + t] - M);
        g_A[b * NND + j0 + j] = M;
        g_iZ[b * NND + j0 + j] = 1.0f / Z;
    }
}

// ---------------- kernel 3: pass 2 — fused attention + back-proj + residual ----------------
// grid (N/128 i-tiles, B), block 256, dynamic smem.
#define S2_KST 0
#define S2_QST (32 * TP)                 // 4224
#define S2_VS  (2 * 32 * TP)             // 8448
#define S2_AS  (S2_VS + 128 * 32)        // 12544
#define S2_P   (S2_AS + 128)             // 12672
#define S2_WB  (S2_P + 128 * 128)        // 29056
#define S2_BB  (S2_WB + 256 * 32)        // 37248
#define S2_TOT (S2_BB + 256)             // 37504 floats = 150016 B

__global__ __launch_bounds__(256, 1) void pass2_kernel(
    const float* __restrict__ x, const float* __restrict__ Wb,
    const float* __restrict__ bbp, float* __restrict__ y)
{
    extern __shared__ float sm[];
    float* ksT = sm + S2_KST;
    float* qsT = sm + S2_QST;
    float* vs  = sm + S2_VS;
    float* As  = sm + S2_AS;
    float* P   = sm + S2_P;
    float* Wbs = sm + S2_WB;
    float* bbs = sm + S2_BB;

    const int tid = threadIdx.x;
    const int b = blockIdx.y;
    const int i0 = blockIdx.x * 128;
    const int tjg = tid >> 4, tig = tid & 15;   // s-gemm mapping
    const int ci = tid >> 5, ii = tid & 31;     // p-gemm mapping

    // stationary: K columns for this i-tile, Wb, bb
    for (int idx = tid; idx < 4096; idx += 256) {
        int i = idx >> 5, kk = idx & 31;
        ksT[kk * TP + i] = g_k[((size_t)(b * NND + i0 + i)) * CPD + kk];
    }
    for (int idx = tid; idx < 256 * 32; idx += 256) Wbs[idx] = Wb[idx];
    if (tid < 256) bbs[tid] = bbp[tid];

    u64 oacc2[4][2];
#pragma unroll
    for (int a = 0; a < 4; a++)
#pragma unroll
        for (int e2 = 0; e2 < 2; e2++) oacc2[a][e2] = 0ULL;

    for (int jt = 0; jt < NND / 128; jt++) {
        __syncthreads();   // previous p-gemm done (vs/qsT free); also covers stationary loads
        const int j0 = jt * 128;
        for (int idx = tid; idx < 4096; idx += 256) {
            int j = idx >> 5, kk = idx & 31;
            qsT[kk * TP + j] = g_q[((size_t)(b * NND + j0 + j)) * CPD + kk];
        }
        for (int idx = tid; idx < 4096; idx += 256) {
            int j = idx >> 5, c = idx & 31;
            int gj = b * NND + j0 + j;
            vs[idx] = g_v[(size_t)gj * CPD + c] * g_iZ[gj];  // fold 1/Z into V
        }
        if (tid < 128) As[tid] = g_A[b * NND + j0 + tid];
        __syncthreads();

        // s-gemm: sacc[j-frag][i-frag]
        u64 sacc2[8][4];
#pragma unroll
        for (int r = 0; r < 8; r++)
#pragma unroll
            for (int c2 = 0; c2 < 4; c2++) sacc2[r][c2] = 0ULL;

#pragma unroll 8
        for (int kk = 0; kk < 32; kk++) {
            float4 a0 = *(const float4*)&qsT[kk * TP + tjg * 8];
            float4 a1 = *(const float4*)&qsT[kk * TP + tjg * 8 + 4];
            ulonglong2 bb0 = *(const ulonglong2*)&ksT[kk * TP + tig * 8];
            ulonglong2 bb1 = *(const ulonglong2*)&ksT[kk * TP + tig * 8 + 4];
            u64 bi2[4] = {bb0.x, bb0.y, bb1.x, bb1.y};
            float aj[8] = {a0.x, a0.y, a0.z, a0.w, a1.x, a1.y, a1.z, a1.w};
#pragma unroll
            for (int r = 0; r < 8; r++) {
                u64 a2 = pack2(aj[r], aj[r]);
#pragma unroll
                for (int c2 = 0; c2 < 4; c2++)
                    sacc2[r][c2] = fma2(a2, bi2[c2], sacc2[r][c2]);
            }
        }

        // P = exp(s - A_j)  (1/Z already folded into vs)
#pragma unroll
        for (int r = 0; r < 8; r++) {
            float a = As[tjg * 8 + r];
            float sv[8];
#pragma unroll
            for (int c2 = 0; c2 < 4; c2++)
                unpack2(sacc2[r][c2], sv[c2 * 2], sv[c2 * 2 + 1]);
            float4 p0, p1;
            p0.x = __expf(sv[0] - a);
            p0.y = __expf(sv[1] - a);
            p0.z = __expf(sv[2] - a);
            p0.w = __expf(sv[3] - a);
            p1.x = __expf(sv[4] - a);
            p1.y = __expf(sv[5] - a);
            p1.z = __expf(sv[6] - a);
            p1.w = __expf(sv[7] - a);
            *(float4*)&P[(tjg * 8 + r) * 128 + tig * 8]     = p0;
            *(float4*)&P[(tjg * 8 + r) * 128 + tig * 8 + 4] = p1;
        }
        __syncthreads();

        // p-gemm: oacc[c-frag][i-frag] += P[j][i] * vs[j][c]
#pragma unroll 2
        for (int j = 0; j < 128; j++) {
            float4 v4 = *(const float4*)&vs[j * 32 + ci * 4];
            ulonglong2 p2 = *(const ulonglong2*)&P[j * 128 + ii * 4];
            u64 pp2[2] = {p2.x, p2.y};
            float vv[4] = {v4.x, v4.y, v4.z, v4.w};
#pragma unroll
            for (int a = 0; a < 4; a++) {
                u64 va = pack2(vv[a], vv[a]);
#pragma unroll
                for (int e2 = 0; e2 < 2; e2++)
                    oacc2[a][e2] = fma2(va, pp2[e2], oacc2[a][e2]);
            }
        }
    }

    // stage out tile [32 x 128] into P region
    __syncthreads();
#pragma unroll
    for (int a = 0; a < 4; a++) {
        float o0, o1, o2, o3;
        unpack2(oacc2[a][0], o0, o1);
        unpack2(oacc2[a][1], o2, o3);
        *(float4*)&P[(ci * 4 + a) * 128 + ii * 4] = make_float4(o0, o1, o2, o3);
    }
    __syncthreads();

    // epilogue: y[b][cf][i] = Wb @ out + bb + x
    const int i = tid & 127;
    const int half = tid >> 7;
    const size_t base = ((size_t)b * CC + half * 128) * NND + i0 + i;
    for (int cf0 = 0; cf0 < 128; cf0++) {
        const int cf = half * 128 + cf0;
        float acc = bbs[cf];
#pragma unroll
        for (int t = 0; t < 32; t += 4) {
            float4 w = *(const float4*)&Wbs[cf * 32 + t];
            acc += w.x * P[(t + 0) * 128 + i];
            acc += w.y * P[(t + 1) * 128 + i];
            acc += w.z * P[(t + 2) * 128 + i];
            acc += w.w * P[(t + 3) * 128 + i];
        }
        const size_t off = base + (size_t)cf0 * NND;
        y[off] = acc + x[off];
    }
}

// ---------------- launcher ----------------
extern "C" void kernel_launch(void* const* d_in, const int* in_sizes, int n_in,
                              void* d_out, int out_size)
{
    const float* x   = (const float*)d_in[0];
    const float* Wq  = (const float*)d_in[1];
    const float* bq  = (const float*)d_in[2];
    const float* Wk  = (const float*)d_in[3];
    const float* bk  = (const float*)d_in[4];
    const float* Wv  = (const float*)d_in[5];
    const float* bv  = (const float*)d_in[6];
    const float* Wb  = (const float*)d_in[7];
    const float* bbp = (const float*)d_in[8];
    float* y = (float*)d_out;

    float *dq, *dk, *dv;
    cudaGetSymbolAddress((void**)&dq, g_q);
    cudaGetSymbolAddress((void**)&dk, g_k);
    cudaGetSymbolAddress((void**)&dv, g_v);

    cudaFuncSetAttribute(pass2_kernel, cudaFuncAttributeMaxDynamicSharedMemorySize,
                         S2_TOT * (int)sizeof(float));

    dim3 gp(NND / 128, BB);
    proj_kernel<<<gp, 128>>>(x, Wq, bq, dq);
    proj_kernel<<<gp, 128>>>(x, Wk, bk, dk);
    proj_kernel<<<gp, 128>>>(x, Wv, bv, dv);
    pass1_kernel<<<dim3(NND / 128, BB), 256>>>();
    pass2_kernel<<<dim3(NND / 128, BB), 256, S2_TOT * sizeof(float)>>>(x, Wb, bbp, y);
}

// round 3
// speedup vs baseline: 1.0654x; 1.0498x over previous
#include <cuda_runtime.h>

#define BB 8
#define CC 256
#define CPD 32
#define NND 4096
#define TP 132   // smem tile pitch (conflict-free-ish, float4-aligned)

typedef unsigned long long u64;

// ---- packed f32x2 helpers (sm_100+) ----
__device__ __forceinline__ u64 pack2(float lo, float hi) {
    u64 r; asm("mov.b64 %0,{%1,%2};" : "=l"(r) : "f"(lo), "f"(hi)); return r;
}
__device__ __forceinline__ u64 fma2(u64 a, u64 b, u64 c) {
    u64 d; asm("fma.rn.f32x2 %0,%1,%2,%3;" : "=l"(d) : "l"(a), "l"(b), "l"(c)); return d;
}
__device__ __forceinline__ void unpack2(u64 v, float& lo, float& hi) {
    asm("mov.b64 {%0,%1},%2;" : "=f"(lo), "=f"(hi) : "l"(v));
}

// ---------------- scratch (__device__ globals; no allocs allowed) ----------------
__device__ float g_q[(size_t)BB * NND * CPD];   // [b][n][cp]  4 MB
__device__ float g_k[(size_t)BB * NND * CPD];
__device__ float g_v[(size_t)BB * NND * CPD];
__device__ float g_A[BB * NND];                 // row max of S (per j)
__device__ float g_iZ[BB * NND];                // 1 / row sum of exp(S - A)

// ---------------- kernel 1: 1x1-conv projection (q/k/v) ----------------
// grid (N/128, B), block 128. out layout [b][n][cp].
__global__ __launch_bounds__(128) void proj_kernel(
    const float* __restrict__ x, const float* __restrict__ W,
    const float* __restrict__ bias, float* __restrict__ out)
{
    __shared__ float Ws[CC * CPD];   // [c][o], 32 KB
    const int tid = threadIdx.x;
    const int b = blockIdx.y;
    const int n = blockIdx.x * 128 + tid;

    for (int idx = tid; idx < CC * CPD; idx += 128)
        Ws[idx] = W[(idx & 31) * CC + (idx >> 5)];
    __syncthreads();

    u64 acc2[CPD / 2];
#pragma unroll
    for (int o2 = 0; o2 < CPD / 2; o2++)
        acc2[o2] = pack2(bias[o2 * 2], bias[o2 * 2 + 1]);

    const float* xp = x + (size_t)b * CC * NND + n;
#pragma unroll 4
    for (int c = 0; c < CC; c++) {
        float xv = __ldg(xp + (size_t)c * NND);
        u64 xv2 = pack2(xv, xv);
        const ulonglong2* w2 = (const ulonglong2*)(Ws + c * CPD);
#pragma unroll
        for (int oq = 0; oq < CPD / 4; oq++) {
            ulonglong2 w = w2[oq];
            acc2[oq * 2 + 0] = fma2(xv2, w.x, acc2[oq * 2 + 0]);
            acc2[oq * 2 + 1] = fma2(xv2, w.y, acc2[oq * 2 + 1]);
        }
    }
    ulonglong2* op = (ulonglong2*)(out + ((size_t)b * NND + n) * CPD);
#pragma unroll
    for (int oq = 0; oq < CPD / 4; oq++) {
        ulonglong2 w; w.x = acc2[oq * 2]; w.y = acc2[oq * 2 + 1];
        op[oq] = w;
    }
}

// ---------------- kernel 2: pass 1 — per-row (A, 1/Z) of softmax(Q^T K) ----------------
// grid (N/128 j-tiles, B), block 256. Thread (tjg,tig) owns 8 j-rows x 8 i-cols.
__global__ __launch_bounds__(256) void pass1_kernel()
{
    __shared__ float sm[2 * 32 * TP];   // qs | ks (kk-major), ~33 KB
    float* qs = sm;
    float* ks = sm + 32 * TP;

    const int tid = threadIdx.x;
    const int b = blockIdx.y;
    const int j0 = blockIdx.x * 128;
    const int tjg = tid >> 4, tig = tid & 15;

    for (int idx = tid; idx < 4096; idx += 256) {
        int j = idx >> 5, kk = idx & 31;
        qs[kk * TP + j] = g_q[((size_t)(b * NND + j0 + j)) * CPD + kk];
    }

    float m[8], z[8];
#pragma unroll
    for (int r = 0; r < 8; r++) { m[r] = -1e30f; z[r] = 0.f; }

    for (int it = 0; it < NND / 128; it++) {
        __syncthreads();
        const int i0 = it * 128;
        for (int idx = tid; idx < 4096; idx += 256) {
            int i = idx >> 5, kk = idx & 31;
            ks[kk * TP + i] = g_k[((size_t)(b * NND + i0 + i)) * CPD + kk];
        }
        __syncthreads();

        u64 sacc2[8][4];
#pragma unroll
        for (int r = 0; r < 8; r++)
#pragma unroll
            for (int c2 = 0; c2 < 4; c2++) sacc2[r][c2] = 0ULL;

#pragma unroll 8
        for (int kk = 0; kk < 32; kk++) {
            float4 a0 = *(const float4*)&qs[kk * TP + tjg * 8];
            float4 a1 = *(const float4*)&qs[kk * TP + tjg * 8 + 4];
            ulonglong2 bb0 = *(const ulonglong2*)&ks[kk * TP + tig * 8];
            ulonglong2 bb1 = *(const ulonglong2*)&ks[kk * TP + tig * 8 + 4];
            u64 bi2[4] = {bb0.x, bb0.y, bb1.x, bb1.y};
            float aj[8] = {a0.x, a0.y, a0.z, a0.w, a1.x, a1.y, a1.z, a1.w};
#pragma unroll
            for (int r = 0; r < 8; r++) {
                u64 a2 = pack2(aj[r], aj[r]);
#pragma unroll
                for (int c2 = 0; c2 < 4; c2++)
                    sacc2[r][c2] = fma2(a2, bi2[c2], sacc2[r][c2]);
            }
        }

#pragma unroll
        for (int r = 0; r < 8; r++) {
            float sv[8];
#pragma unroll
            for (int c2 = 0; c2 < 4; c2++)
                unpack2(sacc2[r][c2], sv[c2 * 2], sv[c2 * 2 + 1]);
            float tm = sv[0];
#pragma unroll
            for (int c = 1; c < 8; c++) tm = fmaxf(tm, sv[c]);
            float mn = fmaxf(m[r], tm);
            float corr = __expf(m[r] - mn);
            float s = 0.f;
#pragma unroll
            for (int c = 0; c < 8; c++) s += __expf(sv[c] - mn);
            z[r] = z[r] * corr + s;
            m[r] = mn;
        }
    }

    // cross-thread (tig) reduction per j-row, staged in the ks region
    __syncthreads();
    float* rm = ks;
    float* rz = ks + 2048;
#pragma unroll
    for (int r = 0; r < 8; r++) {
        int j = tjg * 8 + r;
        rm[j * 16 + tig] = m[r];
        rz[j * 16 + tig] = z[r];
    }
    __syncthreads();
    if (tid < 128) {
        int j = tid;
        float M = -1e30f;
#pragma unroll
        for (int t = 0; t < 16; t++) M = fmaxf(M, rm[j * 16 + t]);
        float Z = 0.f;
#pragma unroll
        for (int t = 0; t < 16; t++) Z += rz[j * 16 + t] * __expf(rm[j * 16 + t] - M);
        g_A[b * NND + j0 + j] = M;
        g_iZ[b * NND + j0 + j] = 1.0f / Z;
    }
}

// ---------------- kernel 3: pass 2 — fused attention + back-proj + residual ----------------
// grid (N/128 i-tiles, B), block 256, dynamic smem.
#define S2_KST 0
#define S2_QST (32 * TP)                 // 4224
#define S2_VS  (2 * 32 * TP)             // 8448
#define S2_AS  (S2_VS + 128 * 32)        // 12544
#define S2_P   (S2_AS + 128)             // 12672
#define S2_WB  (S2_P + 128 * 128)        // 29056
#define S2_BB  (S2_WB + 256 * 32)        // 37248
#define S2_TOT (S2_BB + 256)             // 37504 floats = 150016 B

__global__ __launch_bounds__(256, 1) void pass2_kernel(
    const float* __restrict__ x, const float* __restrict__ Wb,
    const float* __restrict__ bbp, float* __restrict__ y)
{
    extern __shared__ float sm[];
    float* ksT = sm + S2_KST;
    float* qsT = sm + S2_QST;
    float* vs  = sm + S2_VS;
    float* As  = sm + S2_AS;
    float* P   = sm + S2_P;
    float* Wbs = sm + S2_WB;
    float* bbs = sm + S2_BB;

    const int tid = threadIdx.x;
    const int b = blockIdx.y;
    const int i0 = blockIdx.x * 128;
    const int tjg = tid >> 4, tig = tid & 15;   // s-gemm mapping
    const int ci = tid >> 5, ii = tid & 31;     // p-gemm mapping

    // stationary: K columns for this i-tile, Wb, bb
    for (int idx = tid; idx < 4096; idx += 256) {
        int i = idx >> 5, kk = idx & 31;
        ksT[kk * TP + i] = g_k[((size_t)(b * NND + i0 + i)) * CPD + kk];
    }
    for (int idx = tid; idx < 256 * 32; idx += 256) Wbs[idx] = Wb[idx];
    if (tid < 256) bbs[tid] = bbp[tid];

    u64 oacc2[4][2];
#pragma unroll
    for (int a = 0; a < 4; a++)
#pragma unroll
        for (int e2 = 0; e2 < 2; e2++) oacc2[a][e2] = 0ULL;

    for (int jt = 0; jt < NND / 128; jt++) {
        __syncthreads();   // previous p-gemm done (vs/qsT free); also covers stationary loads
        const int j0 = jt * 128;
        for (int idx = tid; idx < 4096; idx += 256) {
            int j = idx >> 5, kk = idx & 31;
            qsT[kk * TP + j] = g_q[((size_t)(b * NND + j0 + j)) * CPD + kk];
        }
        for (int idx = tid; idx < 4096; idx += 256) {
            int j = idx >> 5, c = idx & 31;
            int gj = b * NND + j0 + j;
            vs[idx] = g_v[(size_t)gj * CPD + c] * g_iZ[gj];  // fold 1/Z into V
        }
        if (tid < 128) As[tid] = g_A[b * NND + j0 + tid];
        __syncthreads();

        // s-gemm: sacc[j-frag][i-frag]
        u64 sacc2[8][4];
#pragma unroll
        for (int r = 0; r < 8; r++)
#pragma unroll
            for (int c2 = 0; c2 < 4; c2++) sacc2[r][c2] = 0ULL;

#pragma unroll 8
        for (int kk = 0; kk < 32; kk++) {
            float4 a0 = *(const float4*)&qsT[kk * TP + tjg * 8];
            float4 a1 = *(const float4*)&qsT[kk * TP + tjg * 8 + 4];
            ulonglong2 bb0 = *(const ulonglong2*)&ksT[kk * TP + tig * 8];
            ulonglong2 bb1 = *(const ulonglong2*)&ksT[kk * TP + tig * 8 + 4];
            u64 bi2[4] = {bb0.x, bb0.y, bb1.x, bb1.y};
            float aj[8] = {a0.x, a0.y, a0.z, a0.w, a1.x, a1.y, a1.z, a1.w};
#pragma unroll
            for (int r = 0; r < 8; r++) {
                u64 a2 = pack2(aj[r], aj[r]);
#pragma unroll
                for (int c2 = 0; c2 < 4; c2++)
                    sacc2[r][c2] = fma2(a2, bi2[c2], sacc2[r][c2]);
            }
        }

        // P = exp(s - A_j)  (1/Z already folded into vs)
#pragma unroll
        for (int r = 0; r < 8; r++) {
            float a = As[tjg * 8 + r];
            float sv[8];
#pragma unroll
            for (int c2 = 0; c2 < 4; c2++)
                unpack2(sacc2[r][c2], sv[c2 * 2], sv[c2 * 2 + 1]);
            float4 p0, p1;
            p0.x = __expf(sv[0] - a);
            p0.y = __expf(sv[1] - a);
            p0.z = __expf(sv[2] - a);
            p0.w = __expf(sv[3] - a);
            p1.x = __expf(sv[4] - a);
            p1.y = __expf(sv[5] - a);
            p1.z = __expf(sv[6] - a);
            p1.w = __expf(sv[7] - a);
            *(float4*)&P[(tjg * 8 + r) * 128 + tig * 8]     = p0;
            *(float4*)&P[(tjg * 8 + r) * 128 + tig * 8 + 4] = p1;
        }
        __syncthreads();

        // p-gemm: oacc[c-frag][i-frag] += P[j][i] * vs[j][c]
#pragma unroll 2
        for (int j = 0; j < 128; j++) {
            float4 v4 = *(const float4*)&vs[j * 32 + ci * 4];
            ulonglong2 p2 = *(const ulonglong2*)&P[j * 128 + ii * 4];
            u64 pp2[2] = {p2.x, p2.y};
            float vv[4] = {v4.x, v4.y, v4.z, v4.w};
#pragma unroll
            for (int a = 0; a < 4; a++) {
                u64 va = pack2(vv[a], vv[a]);
#pragma unroll
                for (int e2 = 0; e2 < 2; e2++)
                    oacc2[a][e2] = fma2(va, pp2[e2], oacc2[a][e2]);
            }
        }
    }

    // stage out tile [32 x 128] into P region
    __syncthreads();
#pragma unroll
    for (int a = 0; a < 4; a++) {
        float o0, o1, o2, o3;
        unpack2(oacc2[a][0], o0, o1);
        unpack2(oacc2[a][1], o2, o3);
        *(float4*)&P[(ci * 4 + a) * 128 + ii * 4] = make_float4(o0, o1, o2, o3);
    }
    __syncthreads();

    // epilogue: y[b][cf][i] = Wb @ out + bb + x
    const int i = tid & 127;
    const int half = tid >> 7;
    const size_t base = ((size_t)b * CC + half * 128) * NND + i0 + i;
    for (int cf0 = 0; cf0 < 128; cf0++) {
        const int cf = half * 128 + cf0;
        float acc = bbs[cf];
#pragma unroll
        for (int t = 0; t < 32; t += 4) {
            float4 w = *(const float4*)&Wbs[cf * 32 + t];
            acc += w.x * P[(t + 0) * 128 + i];
            acc += w.y * P[(t + 1) * 128 + i];
            acc += w.z * P[(t + 2) * 128 + i];
            acc += w.w * P[(t + 3) * 128 + i];
        }
        const size_t off = base + (size_t)cf0 * NND;
        y[off] = acc + x[off];
    }
}

// ---------------- launcher ----------------
extern "C" void kernel_launch(void* const* d_in, const int* in_sizes, int n_in,
                              void* d_out, int out_size)
{
    const float* x   = (const float*)d_in[0];
    const float* Wq  = (const float*)d_in[1];
    const float* bq  = (const float*)d_in[2];
    const float* Wk  = (const float*)d_in[3];
    const float* bk  = (const float*)d_in[4];
    const float* Wv  = (const float*)d_in[5];
    const float* bv  = (const float*)d_in[6];
    const float* Wb  = (const float*)d_in[7];
    const float* bbp = (const float*)d_in[8];
    float* y = (float*)d_out;

    float *dq, *dk, *dv;
    cudaGetSymbolAddress((void**)&dq, g_q);
    cudaGetSymbolAddress((void**)&dk, g_k);
    cudaGetSymbolAddress((void**)&dv, g_v);

    cudaFuncSetAttribute(pass2_kernel, cudaFuncAttributeMaxDynamicSharedMemorySize,
                         S2_TOT * (int)sizeof(float));

    dim3 gp(NND / 128, BB);
    proj_kernel<<<gp, 128>>>(x, Wq, bq, dq);
    proj_kernel<<<gp, 128>>>(x, Wk, bk, dk);
    proj_kernel<<<gp, 128>>>(x, Wv, bv, dv);
    pass1_kernel<<<dim3(NND / 128, BB), 256>>>();
    pass2_kernel<<<dim3(NND / 128, BB), 256, S2_TOT * sizeof(float)>>>(x, Wb, bbp, y);
}

// round 8
// speedup vs baseline: 1.7100x; 1.6050x over previous
#include <cuda_runtime.h>
#include <cstdint>

typedef unsigned int u32;
typedef unsigned short u16;

#define BB 8
#define CC 256
#define CPD 32
#define NN 4096
#define PW 36   // Qs/Ks row pitch in words (144B)

// ======================= helpers =======================
__device__ __forceinline__ u32 smem_to_u32(const void* p) {
    u32 a;
    asm("{ .reg .u64 t; cvta.to.shared.u64 t, %1; cvt.u32.u64 %0, t; }" : "=r"(a) : "l"(p));
    return a;
}
__device__ __forceinline__ void mma_bf16(float d[4], const u32 a[4], u32 b0, u32 b1) {
    asm volatile("mma.sync.aligned.m16n8k16.row.col.f32.bf16.bf16.f32 "
        "{%0,%1,%2,%3},{%4,%5,%6,%7},{%8,%9},{%0,%1,%2,%3};"
        : "+f"(d[0]), "+f"(d[1]), "+f"(d[2]), "+f"(d[3])
        : "r"(a[0]), "r"(a[1]), "r"(a[2]), "r"(a[3]), "r"(b0), "r"(b1));
}
__device__ __forceinline__ void ldsm4(u32 r[4], u32 addr) {
    asm volatile("ldmatrix.sync.aligned.m8n8.x4.shared.b16 {%0,%1,%2,%3},[%4];"
        : "=r"(r[0]), "=r"(r[1]), "=r"(r[2]), "=r"(r[3]) : "r"(addr));
}
__device__ __forceinline__ u16 f2bf(float f) {
    u16 r; asm("cvt.rn.bf16.f32 %0,%1;" : "=h"(r) : "f"(f)); return r;
}
__device__ __forceinline__ float bf2f(u16 h) { return __uint_as_float(((u32)h) << 16); }
__device__ __forceinline__ u32 packbf(float lo, float hi) {
    u32 r; asm("cvt.rn.bf16x2.f32 %0,%1,%2;" : "=r"(r) : "f"(hi), "f"(lo)); return r;
}
__device__ __forceinline__ u32 packlo(u32 hipair, float p0, float p1) {
    float h0 = __uint_as_float((hipair & 0xffffu) << 16);
    float h1 = __uint_as_float(hipair & 0xffff0000u);
    return packbf(p0 - h0, p1 - h1);
}

// ======================= scratch (uint4-typed => 16B-aligned) =======================
__device__ uint4 g_q4[(size_t)BB * NN * 8];          // [b][n] rows of 64 halves (hi32|lo32)
__device__ uint4 g_k4[(size_t)BB * NN * 8];
__device__ uint4 g_vh4[(size_t)BB * CPD * NN / 8];   // [b][c][n] bf16 hi
__device__ uint4 g_vl4[(size_t)BB * CPD * NN / 8];   // [b][c][n] bf16 lo
__device__ float2 g_AZ[BB * NN];                     // (rowmax, 1/Z)

// ======================= proj: q/k (split bf16 rows) =======================
__global__ __launch_bounds__(128) void proj_qk_kernel(
    const float* __restrict__ x, const float* __restrict__ W,
    const float* __restrict__ bias, uint4* __restrict__ out)
{
    __shared__ float Ws[CC * CPD];
    const int tid = threadIdx.x, b = blockIdx.y;
    const int n = blockIdx.x * 128 + tid;

    for (int idx = tid; idx < CC * CPD; idx += 128)
        Ws[idx] = W[(idx & 31) * CC + (idx >> 5)];
    __syncthreads();

    float acc[CPD];
#pragma unroll
    for (int o = 0; o < CPD; o++) acc[o] = bias[o];
    const float* xp = x + (size_t)b * CC * NN + n;
#pragma unroll 4
    for (int c = 0; c < CC; c++) {
        float xv = __ldg(xp + (size_t)c * NN);
        const float4* w4 = (const float4*)(Ws + c * CPD);
#pragma unroll
        for (int oq = 0; oq < CPD / 4; oq++) {
            float4 w = w4[oq];
            acc[oq * 4 + 0] += w.x * xv; acc[oq * 4 + 1] += w.y * xv;
            acc[oq * 4 + 2] += w.z * xv; acc[oq * 4 + 3] += w.w * xv;
        }
    }
    u32 wout[32];
#pragma unroll
    for (int o2 = 0; o2 < 16; o2++) {
        u16 h0 = f2bf(acc[2 * o2]), h1 = f2bf(acc[2 * o2 + 1]);
        wout[o2] = (u32)h0 | ((u32)h1 << 16);
        u16 g0 = f2bf(acc[2 * o2] - bf2f(h0));
        u16 g1 = f2bf(acc[2 * o2 + 1] - bf2f(h1));
        wout[16 + o2] = (u32)g0 | ((u32)g1 << 16);
    }
    uint4* op = out + (size_t)(b * NN + n) * 8;
#pragma unroll
    for (int q = 0; q < 8; q++)
        op[q] = make_uint4(wout[q * 4], wout[q * 4 + 1], wout[q * 4 + 2], wout[q * 4 + 3]);
}

// ======================= proj: v (split bf16, [b][c][n]) =======================
__global__ __launch_bounds__(128) void proj_v_kernel(
    const float* __restrict__ x, const float* __restrict__ W,
    const float* __restrict__ bias, u16* __restrict__ outh, u16* __restrict__ outl)
{
    __shared__ float Ws[CC * CPD];
    const int tid = threadIdx.x, b = blockIdx.y;
    const int n = blockIdx.x * 128 + tid;

    for (int idx = tid; idx < CC * CPD; idx += 128)
        Ws[idx] = W[(idx & 31) * CC + (idx >> 5)];
    __syncthreads();

    float acc[CPD];
#pragma unroll
    for (int o = 0; o < CPD; o++) acc[o] = bias[o];
    const float* xp = x + (size_t)b * CC * NN + n;
#pragma unroll 4
    for (int c = 0; c < CC; c++) {
        float xv = __ldg(xp + (size_t)c * NN);
        const float4* w4 = (const float4*)(Ws + c * CPD);
#pragma unroll
        for (int oq = 0; oq < CPD / 4; oq++) {
            float4 w = w4[oq];
            acc[oq * 4 + 0] += w.x * xv; acc[oq * 4 + 1] += w.y * xv;
            acc[oq * 4 + 2] += w.z * xv; acc[oq * 4 + 3] += w.w * xv;
        }
    }
#pragma unroll
    for (int c = 0; c < CPD; c++) {
        u16 h = f2bf(acc[c]);
        outh[((size_t)(b * CPD + c)) * NN + n] = h;
        outl[((size_t)(b * CPD + c)) * NN + n] = f2bf(acc[c] - bf2f(h));
    }
}

// ======================= pass 1: per-row (max, 1/Z) of softmax(Q^T K) =======================
__global__ __launch_bounds__(256) void pass1_kernel()
{
    __shared__ __align__(16) u32 Qs[128 * PW];
    __shared__ __align__(16) u32 Ks[128 * PW];
    const int tid = threadIdx.x, w = tid >> 5, lane = tid & 31;
    const int b = blockIdx.y, j0 = blockIdx.x * 128;

    for (int idx = tid; idx < 1024; idx += 256) {
        int row = idx >> 3, q = idx & 7;
        uint4 v = g_q4[(size_t)(b * NN + j0 + row) * 8 + q];
        *(uint4*)((char*)Qs + row * 144 + q * 16) = v;
    }
    __syncthreads();

    u32 Ah[2][4], Al[2][4];
    {
        int r = (lane & 7) + ((lane >> 3) & 1) * 8;
        u32 base = smem_to_u32(Qs) + (u32)((w * 16 + r) * 144 + (lane >> 4) * 16);
        ldsm4(Ah[0], base);      ldsm4(Ah[1], base + 32);
        ldsm4(Al[0], base + 64); ldsm4(Al[1], base + 96);
    }

    float m0 = -1e30f, m1 = -1e30f, z0 = 0.f, z1 = 0.f;
    for (int it = 0; it < 32; it++) {
        __syncthreads();
        for (int idx = tid; idx < 1024; idx += 256) {
            int row = idx >> 3, q = idx & 7;
            uint4 v = g_k4[(size_t)(b * NN + it * 128 + row) * 8 + q];
            *(uint4*)((char*)Ks + row * 144 + q * 16) = v;
        }
        __syncthreads();

        float dS[16][4];
#pragma unroll
        for (int nf = 0; nf < 16; nf++) {
#pragma unroll
            for (int r = 0; r < 4; r++) dS[nf][r] = 0.f;
            const u32* kr = Ks + (nf * 8 + (lane >> 2)) * PW;
            const int ws = lane & 3;
            u32 bh0 = kr[ws],      bh1 = kr[ws + 4];
            u32 bh2 = kr[ws + 8],  bh3 = kr[ws + 12];
            u32 bl0 = kr[ws + 16], bl1 = kr[ws + 20];
            u32 bl2 = kr[ws + 24], bl3 = kr[ws + 28];
            mma_bf16(dS[nf], Ah[0], bh0, bh1);
            mma_bf16(dS[nf], Ah[1], bh2, bh3);
            mma_bf16(dS[nf], Ah[0], bl0, bl1);
            mma_bf16(dS[nf], Ah[1], bl2, bl3);
            mma_bf16(dS[nf], Al[0], bh0, bh1);
            mma_bf16(dS[nf], Al[1], bh2, bh3);
        }
        float ml0 = -1e30f, ml1 = -1e30f;
#pragma unroll
        for (int nf = 0; nf < 16; nf++) {
            ml0 = fmaxf(ml0, fmaxf(dS[nf][0], dS[nf][1]));
            ml1 = fmaxf(ml1, fmaxf(dS[nf][2], dS[nf][3]));
        }
        float mn0 = fmaxf(m0, ml0), mn1 = fmaxf(m1, ml1);
        float s0 = z0 * __expf(m0 - mn0), s1 = z1 * __expf(m1 - mn1);
#pragma unroll
        for (int nf = 0; nf < 16; nf++) {
            s0 += __expf(dS[nf][0] - mn0) + __expf(dS[nf][1] - mn0);
            s1 += __expf(dS[nf][2] - mn1) + __expf(dS[nf][3] - mn1);
        }
        m0 = mn0; z0 = s0; m1 = mn1; z1 = s1;
    }

#pragma unroll
    for (int off = 1; off <= 2; off <<= 1) {
        float om = __shfl_xor_sync(0xffffffff, m0, off);
        float oz = __shfl_xor_sync(0xffffffff, z0, off);
        float mn = fmaxf(m0, om);
        z0 = z0 * __expf(m0 - mn) + oz * __expf(om - mn);
        m0 = mn;
        om = __shfl_xor_sync(0xffffffff, m1, off);
        oz = __shfl_xor_sync(0xffffffff, z1, off);
        mn = fmaxf(m1, om);
        z1 = z1 * __expf(m1 - mn) + oz * __expf(om - mn);
        m1 = mn;
    }
    if ((lane & 3) == 0) {
        int j = j0 + w * 16 + (lane >> 2);
        g_AZ[b * NN + j] = make_float2(m0, 1.f / z0);
        g_AZ[b * NN + j + 8] = make_float2(m1, 1.f / z1);
    }
}

// ======================= pass 2: attention + back-proj + residual =======================
#define P2_KS  0        // 128*144 = 18432
#define P2_QS  18432    // 18432
#define P2_VS  36864    // 64 rows * 272B = 17408 (rows 0-31 Vh, 32-63 Vl)
#define P2_AZ  54272    // 1024
#define P2_WB  55296    // 32768
#define P2_BS  88064    // 1024
#define P2_PH  89088    // 128 rows * 272B = 34816 (P hi plane)
#define P2_PL  123904   // 34816 (P lo plane)
#define P2_TOT 158720
#define P2_OST 0        // reuse Ks region for output staging

__global__ __launch_bounds__(256) void pass2_kernel(
    const float* __restrict__ x, const float* __restrict__ Wb,
    const float* __restrict__ bbp, float* __restrict__ y)
{
    extern __shared__ char sm2[];
    u32* Ks = (u32*)(sm2 + P2_KS);
    u32* Qs = (u32*)(sm2 + P2_QS);
    u32* Vs = (u32*)(sm2 + P2_VS);
    float2* AZs = (float2*)(sm2 + P2_AZ);
    float* Wbs = (float*)(sm2 + P2_WB);
    float* bbs = (float*)(sm2 + P2_BS);
    float* ost = (float*)(sm2 + P2_OST);
    const u32 sb2 = smem_to_u32(sm2);

    const int tid = threadIdx.x, w = tid >> 5, lane = tid & 31;
    const int b = blockIdx.y, i0 = blockIdx.x * 128;

    for (int idx = tid; idx < 1024; idx += 256) {
        int row = idx >> 3, q = idx & 7;
        uint4 v = g_k4[(size_t)(b * NN + i0 + row) * 8 + q];
        *(uint4*)((char*)Ks + row * 144 + q * 16) = v;
    }
    for (int idx = tid; idx < CC * CPD; idx += 256) Wbs[idx] = Wb[idx];
    if (tid < CC) bbs[tid] = bbp[tid];
    __syncthreads();

    u32 KAh[2][4], KAl[2][4];
    {
        int r = (lane & 7) + ((lane >> 3) & 1) * 8;
        u32 base = sb2 + P2_KS + (u32)((w * 16 + r) * 144 + (lane >> 4) * 16);
        ldsm4(KAh[0], base);      ldsm4(KAh[1], base + 32);
        ldsm4(KAl[0], base + 64); ldsm4(KAl[1], base + 96);
    }

    float dO[4][4];
#pragma unroll
    for (int cf = 0; cf < 4; cf++)
#pragma unroll
        for (int r = 0; r < 4; r++) dO[cf][r] = 0.f;

    for (int jt = 0; jt < 32; jt++) {
        __syncthreads();
        const int jb = jt * 128;
        for (int idx = tid; idx < 1024; idx += 256) {
            int row = idx >> 3, q = idx & 7;
            uint4 v = g_q4[(size_t)(b * NN + jb + row) * 8 + q];
            *(uint4*)((char*)Qs + row * 144 + q * 16) = v;
        }
        // V tile: 64 rows (32 hi + 32 lo) x 128 halves = 16 uint4 per row
        for (int idx = tid; idx < 1024; idx += 256) {
            int row = idx >> 4, q = idx & 15;
            uint4 v = (row < 32)
                ? g_vh4[(((size_t)(b * CPD + row)) * NN + jb) / 8 + q]
                : g_vl4[(((size_t)(b * CPD + (row - 32))) * NN + jb) / 8 + q];
            *(uint4*)((char*)Vs + row * 272 + q * 16) = v;
        }
        if (tid < 128) AZs[tid] = g_AZ[b * NN + jb + tid];
        __syncthreads();

        // ---- S phase: compute S tile, exp, store P hi/lo to smem ----
#pragma unroll
        for (int jp = 0; jp < 8; jp++) {
            float d0[4] = {0.f, 0.f, 0.f, 0.f}, d1[4] = {0.f, 0.f, 0.f, 0.f};
            {
                const u32* qr = Qs + (jp * 16 + (lane >> 2)) * PW;
                const int ws = lane & 3;
                u32 bh0 = qr[ws],      bh1 = qr[ws + 4];
                u32 bh2 = qr[ws + 8],  bh3 = qr[ws + 12];
                u32 bl0 = qr[ws + 16], bl1 = qr[ws + 20];
                u32 bl2 = qr[ws + 24], bl3 = qr[ws + 28];
                mma_bf16(d0, KAh[0], bh0, bh1); mma_bf16(d0, KAh[1], bh2, bh3);
                mma_bf16(d0, KAh[0], bl0, bl1); mma_bf16(d0, KAh[1], bl2, bl3);
                mma_bf16(d0, KAl[0], bh0, bh1); mma_bf16(d0, KAl[1], bh2, bh3);
            }
            {
                const u32* qr = Qs + (jp * 16 + 8 + (lane >> 2)) * PW;
                const int ws = lane & 3;
                u32 bh0 = qr[ws],      bh1 = qr[ws + 4];
                u32 bh2 = qr[ws + 8],  bh3 = qr[ws + 12];
                u32 bl0 = qr[ws + 16], bl1 = qr[ws + 20];
                u32 bl2 = qr[ws + 24], bl3 = qr[ws + 28];
                mma_bf16(d1, KAh[0], bh0, bh1); mma_bf16(d1, KAh[1], bh2, bh3);
                mma_bf16(d1, KAh[0], bl0, bl1); mma_bf16(d1, KAh[1], bl2, bl3);
                mma_bf16(d1, KAl[0], bh0, bh1); mma_bf16(d1, KAl[1], bh2, bh3);
            }
            const int c0 = jp * 16 + 2 * (lane & 3);
            float2 az0 = AZs[c0],     az1 = AZs[c0 + 1];
            float2 az2 = AZs[c0 + 8], az3 = AZs[c0 + 9];
            float p00 = __expf(fminf(d0[0] - az0.x, 80.f)) * az0.y;
            float p01 = __expf(fminf(d0[1] - az1.x, 80.f)) * az1.y;
            float p02 = __expf(fminf(d0[2] - az0.x, 80.f)) * az0.y;
            float p03 = __expf(fminf(d0[3] - az1.x, 80.f)) * az1.y;
            float p10 = __expf(fminf(d1[0] - az2.x, 80.f)) * az2.y;
            float p11 = __expf(fminf(d1[1] - az3.x, 80.f)) * az3.y;
            float p12 = __expf(fminf(d1[2] - az2.x, 80.f)) * az2.y;
            float p13 = __expf(fminf(d1[3] - az3.x, 80.f)) * az3.y;

            const int irow = w * 16 + (lane >> 2);
            u32* ph  = (u32*)(sm2 + P2_PH + irow * 272);
            u32* ph8 = (u32*)(sm2 + P2_PH + (irow + 8) * 272);
            u32* pl  = (u32*)(sm2 + P2_PL + irow * 272);
            u32* pl8 = (u32*)(sm2 + P2_PL + (irow + 8) * 272);
            const int wo = jp * 8 + (lane & 3);
            u32 hp;
            hp = packbf(p00, p01); ph[wo] = hp;      pl[wo] = packlo(hp, p00, p01);
            hp = packbf(p02, p03); ph8[wo] = hp;     pl8[wo] = packlo(hp, p02, p03);
            hp = packbf(p10, p11); ph[wo + 4] = hp;  pl[wo + 4] = packlo(hp, p10, p11);
            hp = packbf(p12, p13); ph8[wo + 4] = hp; pl8[wo + 4] = packlo(hp, p12, p13);
        }
        __syncwarp();

        // ---- PV phase: ldmatrix P back as A operand, V from smem as B ----
#pragma unroll
        for (int jq = 0; jq < 8; jq++) {
            u32 PAh[4], PAl[4];
            int r = (lane & 7) + ((lane >> 3) & 1) * 8;
            u32 pb = sb2 + P2_PH + (u32)((w * 16 + r) * 272 + jq * 32 + (lane >> 4) * 16);
            ldsm4(PAh, pb);
            ldsm4(PAl, pb + (P2_PL - P2_PH));
            const int ws2 = jq * 8 + (lane & 3);
#pragma unroll
            for (int cf = 0; cf < 4; cf++) {
                const u32* vh = Vs + (cf * 8 + (lane >> 2)) * 68;
                const u32* vl = vh + 32 * 68;
                u32 bh0 = vh[ws2], bh1 = vh[ws2 + 4];
                u32 bl0 = vl[ws2], bl1 = vl[ws2 + 4];
                mma_bf16(dO[cf], PAh, bh0, bh1);
                mma_bf16(dO[cf], PAl, bh0, bh1);
                mma_bf16(dO[cf], PAh, bl0, bl1);
            }
        }
    }

    // stage dO -> ost[c][i] (reuses Ks region; KA no longer needed)
    __syncthreads();
#pragma unroll
    for (int cf = 0; cf < 4; cf++) {
        int c = cf * 8 + 2 * (lane & 3);
        int ig = w * 16 + (lane >> 2);
        ost[c * 132 + ig]           = dO[cf][0];
        ost[(c + 1) * 132 + ig]     = dO[cf][1];
        ost[c * 132 + ig + 8]       = dO[cf][2];
        ost[(c + 1) * 132 + ig + 8] = dO[cf][3];
    }
    __syncthreads();

    // epilogue: y[b][cf][i0+i] = Wb @ out + bb + x
    const int i = tid & 127;
    const int half = tid >> 7;
    const size_t base = ((size_t)b * CC + half * 128) * NN + i0 + i;
    for (int cf0 = 0; cf0 < 128; cf0++) {
        const int cf = half * 128 + cf0;
        float acc = bbs[cf];
#pragma unroll
        for (int t = 0; t < 32; t += 4) {
            float4 wv = *(const float4*)&Wbs[cf * 32 + t];
            acc += wv.x * ost[(t + 0) * 132 + i];
            acc += wv.y * ost[(t + 1) * 132 + i];
            acc += wv.z * ost[(t + 2) * 132 + i];
            acc += wv.w * ost[(t + 3) * 132 + i];
        }
        const size_t off = base + (size_t)cf0 * NN;
        y[off] = acc + x[off];
    }
}

// ======================= launcher =======================
extern "C" void kernel_launch(void* const* d_in, const int* in_sizes, int n_in,
                              void* d_out, int out_size)
{
    const float* x   = (const float*)d_in[0];
    const float* Wq  = (const float*)d_in[1];
    const float* bq  = (const float*)d_in[2];
    const float* Wk  = (const float*)d_in[3];
    const float* bk  = (const float*)d_in[4];
    const float* Wv  = (const float*)d_in[5];
    const float* bv  = (const float*)d_in[6];
    const float* Wb  = (const float*)d_in[7];
    const float* bbp = (const float*)d_in[8];
    float* y = (float*)d_out;

    uint4 *dq, *dk, *dvh, *dvl;
    cudaGetSymbolAddress((void**)&dq,  g_q4);
    cudaGetSymbolAddress((void**)&dk,  g_k4);
    cudaGetSymbolAddress((void**)&dvh, g_vh4);
    cudaGetSymbolAddress((void**)&dvl, g_vl4);

    cudaFuncSetAttribute(pass2_kernel, cudaFuncAttributeMaxDynamicSharedMemorySize, P2_TOT);

    dim3 gp(NN / 128, BB);
    proj_qk_kernel<<<gp, 128>>>(x, Wq, bq, dq);
    proj_qk_kernel<<<gp, 128>>>(x, Wk, bk, dk);
    proj_v_kernel<<<gp, 128>>>(x, Wv, bv, (u16*)dvh, (u16*)dvl);
    pass1_kernel<<<gp, 256>>>();
    pass2_kernel<<<gp, 256, P2_TOT>>>(x, Wb, bbp, y);
}

// round 9
// speedup vs baseline: 2.5575x; 1.4957x over previous
#include <cuda_runtime.h>
#include <cstdint>

typedef unsigned int u32;
typedef unsigned short u16;

#define BB 8
#define CC 256
#define CPD 32
#define NN 4096
#define PW 36   // Qs/Ks row pitch in words (144B)
#define LOG2E 1.4426950408889634f

// ======================= helpers =======================
__device__ __forceinline__ u32 smem_to_u32(const void* p) {
    u32 a;
    asm("{ .reg .u64 t; cvta.to.shared.u64 t, %1; cvt.u32.u64 %0, t; }" : "=r"(a) : "l"(p));
    return a;
}
__device__ __forceinline__ void mma_bf16(float d[4], const u32 a[4], u32 b0, u32 b1) {
    asm volatile("mma.sync.aligned.m16n8k16.row.col.f32.bf16.bf16.f32 "
        "{%0,%1,%2,%3},{%4,%5,%6,%7},{%8,%9},{%0,%1,%2,%3};"
        : "+f"(d[0]), "+f"(d[1]), "+f"(d[2]), "+f"(d[3])
        : "r"(a[0]), "r"(a[1]), "r"(a[2]), "r"(a[3]), "r"(b0), "r"(b1));
}
__device__ __forceinline__ void ldsm4(u32 r[4], u32 addr) {
    asm volatile("ldmatrix.sync.aligned.m8n8.x4.shared.b16 {%0,%1,%2,%3},[%4];"
        : "=r"(r[0]), "=r"(r[1]), "=r"(r[2]), "=r"(r[3]) : "r"(addr));
}
__device__ __forceinline__ u16 f2bf(float f) {
    u16 r; asm("cvt.rn.bf16.f32 %0,%1;" : "=h"(r) : "f"(f)); return r;
}
__device__ __forceinline__ float bf2f(u16 h) { return __uint_as_float(((u32)h) << 16); }
__device__ __forceinline__ u32 packbf(float lo, float hi) {
    u32 r; asm("cvt.rn.bf16x2.f32 %0,%1,%2;" : "=r"(r) : "f"(hi), "f"(lo)); return r;
}
__device__ __forceinline__ u32 packlo(u32 hipair, float p0, float p1) {
    float h0 = __uint_as_float((hipair & 0xffffu) << 16);
    float h1 = __uint_as_float(hipair & 0xffff0000u);
    return packbf(p0 - h0, p1 - h1);
}
__device__ __forceinline__ float ex2(float x) {
    float r; asm("ex2.approx.f32 %0,%1;" : "=f"(r) : "f"(x)); return r;
}

// ======================= scratch =======================
__device__ uint4 g_q4[(size_t)BB * NN * 8];          // [b][n] 64 halves (hi32|lo32), q pre-scaled by log2e
__device__ uint4 g_k4[(size_t)BB * NN * 8];
__device__ uint4 g_vh4[(size_t)BB * CPD * NN / 8];   // [b][c][n] bf16 hi (post scale_v: v/Z)
__device__ uint4 g_vl4[(size_t)BB * CPD * NN / 8];
__device__ float g_Zp[4][BB * NN];                   // partial Z sums per i-split (deterministic)

// ======================= fused projection q/k/v =======================
// grid (32, 8), block 128, dynamic smem 96KB: Wq|Wk|Wv transposed [c][o]
__global__ __launch_bounds__(128) void proj_fused_kernel(
    const float* __restrict__ x,
    const float* __restrict__ Wq, const float* __restrict__ bq,
    const float* __restrict__ Wk, const float* __restrict__ bk,
    const float* __restrict__ Wv, const float* __restrict__ bv,
    uint4* __restrict__ outq, uint4* __restrict__ outk,
    u16* __restrict__ outvh, u16* __restrict__ outvl)
{
    extern __shared__ float Ws[];   // [3][256][32]
    const int tid = threadIdx.x, b = blockIdx.y;
    const int n = blockIdx.x * 128 + tid;

    for (int idx = tid; idx < CC * CPD; idx += 128) {
        int c = idx >> 5, o = idx & 31;
        Ws[idx]         = Wq[o * CC + c];
        Ws[8192 + idx]  = Wk[o * CC + c];
        Ws[16384 + idx] = Wv[o * CC + c];
    }
    __syncthreads();

    float qa[CPD], ka[CPD], va[CPD];
#pragma unroll
    for (int o = 0; o < CPD; o++) { qa[o] = bq[o]; ka[o] = bk[o]; va[o] = bv[o]; }

    const float* xp = x + (size_t)b * CC * NN + n;
#pragma unroll 2
    for (int c = 0; c < CC; c++) {
        float xv = __ldg(xp + (size_t)c * NN);
        const float4* wq4 = (const float4*)(Ws + c * CPD);
        const float4* wk4 = (const float4*)(Ws + 8192 + c * CPD);
        const float4* wv4 = (const float4*)(Ws + 16384 + c * CPD);
#pragma unroll
        for (int oq = 0; oq < CPD / 4; oq++) {
            float4 a = wq4[oq], k = wk4[oq], v = wv4[oq];
            qa[oq*4+0] += a.x*xv; qa[oq*4+1] += a.y*xv; qa[oq*4+2] += a.z*xv; qa[oq*4+3] += a.w*xv;
            ka[oq*4+0] += k.x*xv; ka[oq*4+1] += k.y*xv; ka[oq*4+2] += k.z*xv; ka[oq*4+3] += k.w*xv;
            va[oq*4+0] += v.x*xv; va[oq*4+1] += v.y*xv; va[oq*4+2] += v.z*xv; va[oq*4+3] += v.w*xv;
        }
    }
#pragma unroll
    for (int o = 0; o < CPD; o++) qa[o] *= LOG2E;   // fold log2e => exp becomes ex2

    // q split rows
    u32 wout[32];
#pragma unroll
    for (int o2 = 0; o2 < 16; o2++) {
        u16 h0 = f2bf(qa[2*o2]), h1 = f2bf(qa[2*o2+1]);
        wout[o2] = (u32)h0 | ((u32)h1 << 16);
        wout[16+o2] = (u32)f2bf(qa[2*o2] - bf2f(h0)) | ((u32)f2bf(qa[2*o2+1] - bf2f(h1)) << 16);
    }
    uint4* opq = outq + (size_t)(b * NN + n) * 8;
#pragma unroll
    for (int q = 0; q < 8; q++)
        opq[q] = make_uint4(wout[q*4], wout[q*4+1], wout[q*4+2], wout[q*4+3]);
    // k split rows
#pragma unroll
    for (int o2 = 0; o2 < 16; o2++) {
        u16 h0 = f2bf(ka[2*o2]), h1 = f2bf(ka[2*o2+1]);
        wout[o2] = (u32)h0 | ((u32)h1 << 16);
        wout[16+o2] = (u32)f2bf(ka[2*o2] - bf2f(h0)) | ((u32)f2bf(ka[2*o2+1] - bf2f(h1)) << 16);
    }
    uint4* opk = outk + (size_t)(b * NN + n) * 8;
#pragma unroll
    for (int q = 0; q < 8; q++)
        opk[q] = make_uint4(wout[q*4], wout[q*4+1], wout[q*4+2], wout[q*4+3]);
    // v split planes (unnormalized; scale_v folds 1/Z later)
#pragma unroll
    for (int c = 0; c < CPD; c++) {
        u16 h = f2bf(va[c]);
        outvh[((size_t)(b * CPD + c)) * NN + n] = h;
        outvl[((size_t)(b * CPD + c)) * NN + n] = f2bf(va[c] - bf2f(h));
    }
}

// ======================= pass 1: Z partial sums (no max; A==0) =======================
// grid (32 j-tiles, 4 i-splits, 8 b), block 256
__global__ __launch_bounds__(256) void pass1_kernel()
{
    __shared__ __align__(16) u32 Qs[128 * PW];
    __shared__ __align__(16) u32 Ks[128 * PW];
    const int tid = threadIdx.x, w = tid >> 5, lane = tid & 31;
    const int b = blockIdx.z, j0 = blockIdx.x * 128, it0 = blockIdx.y * 8;

    for (int idx = tid; idx < 1024; idx += 256) {
        int row = idx >> 3, q = idx & 7;
        uint4 v = g_q4[(size_t)(b * NN + j0 + row) * 8 + q];
        *(uint4*)((char*)Qs + row * 144 + q * 16) = v;
    }
    __syncthreads();

    u32 Ah[2][4], Al[2][4];
    {
        int r = (lane & 7) + ((lane >> 3) & 1) * 8;
        u32 base = smem_to_u32(Qs) + (u32)((w * 16 + r) * 144 + (lane >> 4) * 16);
        ldsm4(Ah[0], base);      ldsm4(Ah[1], base + 32);
        ldsm4(Al[0], base + 64); ldsm4(Al[1], base + 96);
    }

    float z0 = 0.f, z1 = 0.f;
    for (int it = it0; it < it0 + 8; it++) {
        __syncthreads();
        for (int idx = tid; idx < 1024; idx += 256) {
            int row = idx >> 3, q = idx & 7;
            uint4 v = g_k4[(size_t)(b * NN + it * 128 + row) * 8 + q];
            *(uint4*)((char*)Ks + row * 144 + q * 16) = v;
        }
        __syncthreads();

#pragma unroll
        for (int nf = 0; nf < 16; nf++) {
            float d[4] = {0.f, 0.f, 0.f, 0.f};
            const u32* kr = Ks + (nf * 8 + (lane >> 2)) * PW;
            const int ws = lane & 3;
            u32 bh0 = kr[ws],      bh1 = kr[ws + 4];
            u32 bh2 = kr[ws + 8],  bh3 = kr[ws + 12];
            u32 bl0 = kr[ws + 16], bl1 = kr[ws + 20];
            u32 bl2 = kr[ws + 24], bl3 = kr[ws + 28];
            mma_bf16(d, Ah[0], bh0, bh1);
            mma_bf16(d, Ah[1], bh2, bh3);
            mma_bf16(d, Ah[0], bl0, bl1);
            mma_bf16(d, Ah[1], bl2, bl3);
            mma_bf16(d, Al[0], bh0, bh1);
            mma_bf16(d, Al[1], bh2, bh3);
            z0 += ex2(fminf(d[0], 126.f)) + ex2(fminf(d[1], 126.f));
            z1 += ex2(fminf(d[2], 126.f)) + ex2(fminf(d[3], 126.f));
        }
    }

    z0 += __shfl_xor_sync(0xffffffff, z0, 1);
    z0 += __shfl_xor_sync(0xffffffff, z0, 2);
    z1 += __shfl_xor_sync(0xffffffff, z1, 1);
    z1 += __shfl_xor_sync(0xffffffff, z1, 2);
    if ((lane & 3) == 0) {
        int j = j0 + w * 16 + (lane >> 2);
        g_Zp[blockIdx.y][b * NN + j]     = z0;
        g_Zp[blockIdx.y][b * NN + j + 8] = z1;
    }
}

// ======================= scale_v: fold 1/Z into V (deterministic partial merge) =======================
__global__ __launch_bounds__(256) void scale_v_kernel(u16* __restrict__ vh, u16* __restrict__ vl)
{
    const int n = blockIdx.x * 256 + threadIdx.x;
    const int b = blockIdx.y;
    const int o = b * NN + n;
    float Z = g_Zp[0][o] + g_Zp[1][o] + g_Zp[2][o] + g_Zp[3][o];
    float iZ = 1.0f / Z;
#pragma unroll 4
    for (int c = 0; c < CPD; c++) {
        size_t off = ((size_t)(b * CPD + c)) * NN + n;
        float v = (bf2f(vh[off]) + bf2f(vl[off])) * iZ;
        u16 h = f2bf(v);
        vh[off] = h;
        vl[off] = f2bf(v - bf2f(h));
    }
}

// ======================= pass 2: attention + back-proj + residual =======================
#define P2_KS  0        // 18432
#define P2_QS  18432    // 18432
#define P2_VS  36864    // 64 rows * 272B = 17408
#define P2_WB  54272    // 32768
#define P2_BS  87040    // 1024
#define P2_TOT 88064
#define P2_OST 0        // reuse Ks region

__global__ __launch_bounds__(256) void pass2_kernel(
    const float* __restrict__ x, const float* __restrict__ Wb,
    const float* __restrict__ bbp, float* __restrict__ y)
{
    extern __shared__ char sm2[];
    u32* Ks = (u32*)(sm2 + P2_KS);
    u32* Qs = (u32*)(sm2 + P2_QS);
    u32* Vs = (u32*)(sm2 + P2_VS);
    float* Wbs = (float*)(sm2 + P2_WB);
    float* bbs = (float*)(sm2 + P2_BS);
    float* ost = (float*)(sm2 + P2_OST);
    const u32 sb2 = smem_to_u32(sm2);

    const int tid = threadIdx.x, w = tid >> 5, lane = tid & 31;
    const int b = blockIdx.y, i0 = blockIdx.x * 128;

    for (int idx = tid; idx < 1024; idx += 256) {
        int row = idx >> 3, q = idx & 7;
        uint4 v = g_k4[(size_t)(b * NN + i0 + row) * 8 + q];
        *(uint4*)((char*)Ks + row * 144 + q * 16) = v;
    }
    for (int idx = tid; idx < CC * CPD; idx += 256) Wbs[idx] = Wb[idx];
    if (tid < CC) bbs[tid] = bbp[tid];
    __syncthreads();

    u32 KAh[2][4], KAl[2][4];
    {
        int r = (lane & 7) + ((lane >> 3) & 1) * 8;
        u32 base = sb2 + P2_KS + (u32)((w * 16 + r) * 144 + (lane >> 4) * 16);
        ldsm4(KAh[0], base);      ldsm4(KAh[1], base + 32);
        ldsm4(KAl[0], base + 64); ldsm4(KAl[1], base + 96);
    }

    float dO[4][4];
#pragma unroll
    for (int cf = 0; cf < 4; cf++)
#pragma unroll
        for (int r = 0; r < 4; r++) dO[cf][r] = 0.f;

    for (int jt = 0; jt < 32; jt++) {
        __syncthreads();
        const int jb = jt * 128;
        for (int idx = tid; idx < 1024; idx += 256) {
            int row = idx >> 3, q = idx & 7;
            uint4 v = g_q4[(size_t)(b * NN + jb + row) * 8 + q];
            *(uint4*)((char*)Qs + row * 144 + q * 16) = v;
        }
        for (int idx = tid; idx < 1024; idx += 256) {
            int row = idx >> 4, q = idx & 15;
            uint4 v = (row < 32)
                ? g_vh4[(((size_t)(b * CPD + row)) * NN + jb) / 8 + q]
                : g_vl4[(((size_t)(b * CPD + (row - 32))) * NN + jb) / 8 + q];
            *(uint4*)((char*)Vs + row * 272 + q * 16) = v;
        }
        __syncthreads();

#pragma unroll
        for (int jp = 0; jp < 8; jp++) {
            float d0[4] = {0.f, 0.f, 0.f, 0.f}, d1[4] = {0.f, 0.f, 0.f, 0.f};
            {
                const u32* qr = Qs + (jp * 16 + (lane >> 2)) * PW;
                const int ws = lane & 3;
                u32 bh0 = qr[ws],      bh1 = qr[ws + 4];
                u32 bh2 = qr[ws + 8],  bh3 = qr[ws + 12];
                u32 bl0 = qr[ws + 16], bl1 = qr[ws + 20];
                u32 bl2 = qr[ws + 24], bl3 = qr[ws + 28];
                mma_bf16(d0, KAh[0], bh0, bh1); mma_bf16(d0, KAh[1], bh2, bh3);
                mma_bf16(d0, KAh[0], bl0, bl1); mma_bf16(d0, KAh[1], bl2, bl3);
                mma_bf16(d0, KAl[0], bh0, bh1); mma_bf16(d0, KAl[1], bh2, bh3);
            }
            {
                const u32* qr = Qs + (jp * 16 + 8 + (lane >> 2)) * PW;
                const int ws = lane & 3;
                u32 bh0 = qr[ws],      bh1 = qr[ws + 4];
                u32 bh2 = qr[ws + 8],  bh3 = qr[ws + 12];
                u32 bl0 = qr[ws + 16], bl1 = qr[ws + 20];
                u32 bl2 = qr[ws + 24], bl3 = qr[ws + 28];
                mma_bf16(d1, KAh[0], bh0, bh1); mma_bf16(d1, KAh[1], bh2, bh3);
                mma_bf16(d1, KAh[0], bl0, bl1); mma_bf16(d1, KAh[1], bl2, bl3);
                mma_bf16(d1, KAl[0], bh0, bh1); mma_bf16(d1, KAl[1], bh2, bh3);
            }
            // P = exp2(S') unnormalized (1/Z folded into V); chain D->A in registers
            float p00 = ex2(fminf(d0[0], 126.f));
            float p01 = ex2(fminf(d0[1], 126.f));
            float p02 = ex2(fminf(d0[2], 126.f));
            float p03 = ex2(fminf(d0[3], 126.f));
            float p10 = ex2(fminf(d1[0], 126.f));
            float p11 = ex2(fminf(d1[1], 126.f));
            float p12 = ex2(fminf(d1[2], 126.f));
            float p13 = ex2(fminf(d1[3], 126.f));
            u32 aH[4], aL[4];
            aH[0] = packbf(p00, p01); aH[1] = packbf(p02, p03);
            aH[2] = packbf(p10, p11); aH[3] = packbf(p12, p13);
            aL[0] = packlo(aH[0], p00, p01); aL[1] = packlo(aH[1], p02, p03);
            aL[2] = packlo(aH[2], p10, p11); aL[3] = packlo(aH[3], p12, p13);
            const int ws2 = jp * 8 + (lane & 3);
#pragma unroll
            for (int cf = 0; cf < 4; cf++) {
                const u32* vh = Vs + (cf * 8 + (lane >> 2)) * 68;
                const u32* vl = vh + 32 * 68;
                u32 bh0 = vh[ws2], bh1 = vh[ws2 + 4];
                u32 bl0 = vl[ws2], bl1 = vl[ws2 + 4];
                mma_bf16(dO[cf], aH, bh0, bh1);
                mma_bf16(dO[cf], aL, bh0, bh1);
                mma_bf16(dO[cf], aH, bl0, bl1);
            }
        }
    }

    // stage dO -> ost[c][i]
    __syncthreads();
#pragma unroll
    for (int cf = 0; cf < 4; cf++) {
        int c = cf * 8 + 2 * (lane & 3);
        int ig = w * 16 + (lane >> 2);
        ost[c * 132 + ig]           = dO[cf][0];
        ost[(c + 1) * 132 + ig]     = dO[cf][1];
        ost[c * 132 + ig + 8]       = dO[cf][2];
        ost[(c + 1) * 132 + ig + 8] = dO[cf][3];
    }
    __syncthreads();

    // epilogue: y[b][cf][i0+i] = Wb @ out + bb + x
    const int i = tid & 127;
    const int half = tid >> 7;
    const size_t base = ((size_t)b * CC + half * 128) * NN + i0 + i;
    for (int cf0 = 0; cf0 < 128; cf0++) {
        const int cf = half * 128 + cf0;
        float acc = bbs[cf];
#pragma unroll
        for (int t = 0; t < 32; t += 4) {
            float4 wv = *(const float4*)&Wbs[cf * 32 + t];
            acc += wv.x * ost[(t + 0) * 132 + i];
            acc += wv.y * ost[(t + 1) * 132 + i];
            acc += wv.z * ost[(t + 2) * 132 + i];
            acc += wv.w * ost[(t + 3) * 132 + i];
        }
        const size_t off = base + (size_t)cf0 * NN;
        y[off] = acc + x[off];
    }
}

// ======================= launcher =======================
extern "C" void kernel_launch(void* const* d_in, const int* in_sizes, int n_in,
                              void* d_out, int out_size)
{
    const float* x   = (const float*)d_in[0];
    const float* Wq  = (const float*)d_in[1];
    const float* bq  = (const float*)d_in[2];
    const float* Wk  = (const float*)d_in[3];
    const float* bk  = (const float*)d_in[4];
    const float* Wv  = (const float*)d_in[5];
    const float* bv  = (const float*)d_in[6];
    const float* Wb  = (const float*)d_in[7];
    const float* bbp = (const float*)d_in[8];
    float* y = (float*)d_out;

    uint4 *dq, *dk, *dvh, *dvl;
    cudaGetSymbolAddress((void**)&dq,  g_q4);
    cudaGetSymbolAddress((void**)&dk,  g_k4);
    cudaGetSymbolAddress((void**)&dvh, g_vh4);
    cudaGetSymbolAddress((void**)&dvl, g_vl4);

    cudaFuncSetAttribute(proj_fused_kernel, cudaFuncAttributeMaxDynamicSharedMemorySize, 98304);
    cudaFuncSetAttribute(pass2_kernel, cudaFuncAttributeMaxDynamicSharedMemorySize, P2_TOT);

    proj_fused_kernel<<<dim3(NN / 128, BB), 128, 98304>>>(
        x, Wq, bq, Wk, bk, Wv, bv, dq, dk, (u16*)dvh, (u16*)dvl);
    pass1_kernel<<<dim3(NN / 128, 4, BB), 256>>>();
    scale_v_kernel<<<dim3(NN / 256, BB), 256>>>((u16*)dvh, (u16*)dvl);
    pass2_kernel<<<dim3(NN / 128, BB), 256, P2_TOT>>>(x, Wb, bbp, y);
}

// round 10
// speedup vs baseline: 4.1262x; 1.6133x over previous
#include <cuda_runtime.h>
#include <cstdint>

typedef unsigned int u32;
typedef unsigned short u16;

#define BB 8
#define CC 256
#define CPD 32
#define NN 4096
#define QPW 20   // q/k smem row pitch in words (80B; ldmatrix 16B-groups (r*5)%8 all distinct)
#define LOG2E 1.4426950408889634f

// ======================= helpers =======================
__device__ __forceinline__ u32 smem_to_u32(const void* p) {
    u32 a;
    asm("{ .reg .u64 t; cvta.to.shared.u64 t, %1; cvt.u32.u64 %0, t; }" : "=r"(a) : "l"(p));
    return a;
}
__device__ __forceinline__ void mma_f16(float d[4], const u32 a[4], u32 b0, u32 b1) {
    asm volatile("mma.sync.aligned.m16n8k16.row.col.f32.f16.f16.f32 "
        "{%0,%1,%2,%3},{%4,%5,%6,%7},{%8,%9},{%0,%1,%2,%3};"
        : "+f"(d[0]), "+f"(d[1]), "+f"(d[2]), "+f"(d[3])
        : "r"(a[0]), "r"(a[1]), "r"(a[2]), "r"(a[3]), "r"(b0), "r"(b1));
}
__device__ __forceinline__ void ldsm4(u32 r[4], u32 addr) {
    asm volatile("ldmatrix.sync.aligned.m8n8.x4.shared.b16 {%0,%1,%2,%3},[%4];"
        : "=r"(r[0]), "=r"(r[1]), "=r"(r[2]), "=r"(r[3]) : "r"(addr));
}
__device__ __forceinline__ u16 f2h(float f) {
    u16 r; asm("cvt.rn.f16.f32 %0,%1;" : "=h"(r) : "f"(f)); return r;
}
__device__ __forceinline__ u32 packh(float lo, float hi) {
    u32 r; asm("cvt.rn.f16x2.f32 %0,%1,%2;" : "=r"(r) : "f"(hi), "f"(lo)); return r;
}
__device__ __forceinline__ float ex2(float x) {
    float r; asm("ex2.approx.f32 %0,%1;" : "=f"(r) : "f"(x)); return r;
}

// ======================= scratch =======================
__device__ uint4 g_q4[(size_t)BB * NN * 4];          // [b][n] 32 fp16 (pre-scaled by log2e)
__device__ uint4 g_k4[(size_t)BB * NN * 4];          // [b][n] 32 fp16
__device__ float g_vf[(size_t)BB * CPD * NN];        // [b][c][n] f32 (pre-scale)
__device__ uint4 g_vh4[(size_t)BB * CPD * NN / 8];   // [b][c][n] fp16 (post scale_v: v*256/Z)
__device__ float g_Zp[4][BB * NN];                   // partial Z sums (deterministic)
__device__ float g_Op[4][(size_t)BB * 32 * 4096];    // partial O per j-split: [b*32+it][c*128+i]

// ======================= fused projection q/k/v =======================
__global__ __launch_bounds__(128) void proj_fused_kernel(
    const float* __restrict__ x,
    const float* __restrict__ Wq, const float* __restrict__ bq,
    const float* __restrict__ Wk, const float* __restrict__ bk,
    const float* __restrict__ Wv, const float* __restrict__ bv,
    uint4* __restrict__ outq, uint4* __restrict__ outk, float* __restrict__ outvf)
{
    extern __shared__ float Ws[];   // [3][256][32]
    const int tid = threadIdx.x, b = blockIdx.y;
    const int n = blockIdx.x * 128 + tid;

    for (int idx = tid; idx < CC * CPD; idx += 128) {
        int c = idx >> 5, o = idx & 31;
        Ws[idx]         = Wq[o * CC + c];
        Ws[8192 + idx]  = Wk[o * CC + c];
        Ws[16384 + idx] = Wv[o * CC + c];
    }
    __syncthreads();

    float qa[CPD], ka[CPD], va[CPD];
#pragma unroll
    for (int o = 0; o < CPD; o++) { qa[o] = bq[o]; ka[o] = bk[o]; va[o] = bv[o]; }

    const float* xp = x + (size_t)b * CC * NN + n;
#pragma unroll 2
    for (int c = 0; c < CC; c++) {
        float xv = __ldg(xp + (size_t)c * NN);
        const float4* wq4 = (const float4*)(Ws + c * CPD);
        const float4* wk4 = (const float4*)(Ws + 8192 + c * CPD);
        const float4* wv4 = (const float4*)(Ws + 16384 + c * CPD);
#pragma unroll
        for (int oq = 0; oq < CPD / 4; oq++) {
            float4 a = wq4[oq], k = wk4[oq], v = wv4[oq];
            qa[oq*4+0] += a.x*xv; qa[oq*4+1] += a.y*xv; qa[oq*4+2] += a.z*xv; qa[oq*4+3] += a.w*xv;
            ka[oq*4+0] += k.x*xv; ka[oq*4+1] += k.y*xv; ka[oq*4+2] += k.z*xv; ka[oq*4+3] += k.w*xv;
            va[oq*4+0] += v.x*xv; va[oq*4+1] += v.y*xv; va[oq*4+2] += v.z*xv; va[oq*4+3] += v.w*xv;
        }
    }

    u32 wq[16], wk[16];
#pragma unroll
    for (int o2 = 0; o2 < 16; o2++) {
        wq[o2] = packh(qa[2*o2] * LOG2E, qa[2*o2+1] * LOG2E);
        wk[o2] = packh(ka[2*o2], ka[2*o2+1]);
    }
    uint4* opq = outq + (size_t)(b * NN + n) * 4;
    uint4* opk = outk + (size_t)(b * NN + n) * 4;
#pragma unroll
    for (int q = 0; q < 4; q++) {
        opq[q] = make_uint4(wq[q*4], wq[q*4+1], wq[q*4+2], wq[q*4+3]);
        opk[q] = make_uint4(wk[q*4], wk[q*4+1], wk[q*4+2], wk[q*4+3]);
    }
#pragma unroll
    for (int c = 0; c < CPD; c++)
        outvf[((size_t)(b * CPD + c)) * NN + n] = va[c];
}

// ======================= pass 1: Z partial sums =======================
// grid (32 j-tiles, 4 i-splits, 8 b), block 256
__global__ __launch_bounds__(256) void pass1_kernel()
{
    __shared__ __align__(16) u32 Qs[128 * QPW];
    __shared__ __align__(16) u32 Ks[128 * QPW];
    const int tid = threadIdx.x, w = tid >> 5, lane = tid & 31;
    const int b = blockIdx.z, j0 = blockIdx.x * 128, it0 = blockIdx.y * 8;

    for (int idx = tid; idx < 512; idx += 256) {
        int row = idx >> 2, q = idx & 3;
        uint4 v = g_q4[(size_t)(b * NN + j0 + row) * 4 + q];
        *(uint4*)((char*)Qs + row * 80 + q * 16) = v;
    }
    __syncthreads();

    u32 A[2][4];
    {
        int r = (lane & 7) + ((lane >> 3) & 1) * 8;
        u32 base = smem_to_u32(Qs) + (u32)((w * 16 + r) * 80 + (lane >> 4) * 16);
        ldsm4(A[0], base); ldsm4(A[1], base + 32);
    }

    float z0 = 0.f, z1 = 0.f;
    for (int it = it0; it < it0 + 8; it++) {
        __syncthreads();
        for (int idx = tid; idx < 512; idx += 256) {
            int row = idx >> 2, q = idx & 3;
            uint4 v = g_k4[(size_t)(b * NN + it * 128 + row) * 4 + q];
            *(uint4*)((char*)Ks + row * 80 + q * 16) = v;
        }
        __syncthreads();

#pragma unroll
        for (int nf = 0; nf < 16; nf++) {
            float d[4] = {0.f, 0.f, 0.f, 0.f};
            const u32* kr = Ks + (nf * 8 + (lane >> 2)) * QPW;
            const int ws = lane & 3;
            mma_f16(d, A[0], kr[ws], kr[ws + 4]);
            mma_f16(d, A[1], kr[ws + 8], kr[ws + 12]);
            z0 += ex2(fminf(d[0], 126.f)) + ex2(fminf(d[1], 126.f));
            z1 += ex2(fminf(d[2], 126.f)) + ex2(fminf(d[3], 126.f));
        }
    }

    z0 += __shfl_xor_sync(0xffffffff, z0, 1);
    z0 += __shfl_xor_sync(0xffffffff, z0, 2);
    z1 += __shfl_xor_sync(0xffffffff, z1, 1);
    z1 += __shfl_xor_sync(0xffffffff, z1, 2);
    if ((lane & 3) == 0) {
        int j = j0 + w * 16 + (lane >> 2);
        g_Zp[blockIdx.y][b * NN + j]     = z0;
        g_Zp[blockIdx.y][b * NN + j + 8] = z1;
    }
}

// ======================= scale_v: V_fp16 = V_f32 * 2^8 / Z =======================
__global__ __launch_bounds__(256) void scale_v_kernel(u16* __restrict__ vh)
{
    const int n = blockIdx.x * 256 + threadIdx.x;
    const int b = blockIdx.y;
    const int o = b * NN + n;
    float Z = g_Zp[0][o] + g_Zp[1][o] + g_Zp[2][o] + g_Zp[3][o];
    float iZ = 256.0f / Z;
#pragma unroll 4
    for (int c = 0; c < CPD; c++) {
        size_t off = ((size_t)(b * CPD + c)) * NN + n;
        vh[off] = f2h(g_vf[off] * iZ);
    }
}

// ======================= pass 2: S + exp + PV, partial O =======================
// smem: Ks 10240 | Qs 10240 | Vs 8704 -> 29184; ost (f32 32x132=16896B) reuses Ks+Qs
#define P2_KS 0
#define P2_QS 10240
#define P2_VS 20480
#define P2_TOT 29184

__global__ __launch_bounds__(256) void pass2_kernel()
{
    extern __shared__ char sm2[];
    u32* Ks = (u32*)(sm2 + P2_KS);
    u32* Qs = (u32*)(sm2 + P2_QS);
    u32* Vs = (u32*)(sm2 + P2_VS);
    float* ost = (float*)sm2;
    const u32 sb2 = smem_to_u32(sm2);

    const int tid = threadIdx.x, w = tid >> 5, lane = tid & 31;
    const int b = blockIdx.z, i0 = blockIdx.x * 128, js = blockIdx.y;

    for (int idx = tid; idx < 512; idx += 256) {
        int row = idx >> 2, q = idx & 3;
        uint4 v = g_k4[(size_t)(b * NN + i0 + row) * 4 + q];
        *(uint4*)((char*)Ks + row * 80 + q * 16) = v;
    }
    __syncthreads();

    u32 KA[2][4];
    {
        int r = (lane & 7) + ((lane >> 3) & 1) * 8;
        u32 base = sb2 + P2_KS + (u32)((w * 16 + r) * 80 + (lane >> 4) * 16);
        ldsm4(KA[0], base); ldsm4(KA[1], base + 32);
    }

    float dO[4][4];
#pragma unroll
    for (int cf = 0; cf < 4; cf++)
#pragma unroll
        for (int r = 0; r < 4; r++) dO[cf][r] = 0.f;

    for (int jt = js * 8; jt < js * 8 + 8; jt++) {
        __syncthreads();
        const int jb = jt * 128;
        for (int idx = tid; idx < 512; idx += 256) {
            int row = idx >> 2, q = idx & 3;
            uint4 v = g_q4[(size_t)(b * NN + jb + row) * 4 + q];
            *(uint4*)((char*)Qs + row * 80 + q * 16) = v;
        }
        for (int idx = tid; idx < 512; idx += 256) {
            int row = idx >> 4, q = idx & 15;
            uint4 v = g_vh4[(size_t)(b * CPD + row) * (NN / 8) + (jb >> 3) + q];
            *(uint4*)((char*)Vs + row * 272 + q * 16) = v;
        }
        __syncthreads();

#pragma unroll
        for (int jp = 0; jp < 8; jp++) {
            float d0[4] = {0.f, 0.f, 0.f, 0.f}, d1[4] = {0.f, 0.f, 0.f, 0.f};
            const int ws = lane & 3;
            {
                const u32* qr = Qs + (jp * 16 + (lane >> 2)) * QPW;
                mma_f16(d0, KA[0], qr[ws], qr[ws + 4]);
                mma_f16(d0, KA[1], qr[ws + 8], qr[ws + 12]);
            }
            {
                const u32* qr = Qs + (jp * 16 + 8 + (lane >> 2)) * QPW;
                mma_f16(d1, KA[0], qr[ws], qr[ws + 4]);
                mma_f16(d1, KA[1], qr[ws + 8], qr[ws + 12]);
            }
            // P' = exp2(S' - 8), clamp 14 => fits fp16; 2^8 pre-folded into V
            float p00 = ex2(fminf(d0[0] - 8.f, 14.f));
            float p01 = ex2(fminf(d0[1] - 8.f, 14.f));
            float p02 = ex2(fminf(d0[2] - 8.f, 14.f));
            float p03 = ex2(fminf(d0[3] - 8.f, 14.f));
            float p10 = ex2(fminf(d1[0] - 8.f, 14.f));
            float p11 = ex2(fminf(d1[1] - 8.f, 14.f));
            float p12 = ex2(fminf(d1[2] - 8.f, 14.f));
            float p13 = ex2(fminf(d1[3] - 8.f, 14.f));
            u32 aH[4];
            aH[0] = packh(p00, p01); aH[1] = packh(p02, p03);
            aH[2] = packh(p10, p11); aH[3] = packh(p12, p13);
            const int ws2 = jp * 8 + (lane & 3);
#pragma unroll
            for (int cf = 0; cf < 4; cf++) {
                const u32* vh = Vs + (cf * 8 + (lane >> 2)) * 68;
                mma_f16(dO[cf], aH, vh[ws2], vh[ws2 + 4]);
            }
        }
    }

    // stage dO -> ost[c][i], then coalesced partial store
    __syncthreads();
#pragma unroll
    for (int cf = 0; cf < 4; cf++) {
        int c = cf * 8 + 2 * (lane & 3);
        int ig = w * 16 + (lane >> 2);
        ost[c * 132 + ig]           = dO[cf][0];
        ost[(c + 1) * 132 + ig]     = dO[cf][1];
        ost[c * 132 + ig + 8]       = dO[cf][2];
        ost[(c + 1) * 132 + ig + 8] = dO[cf][3];
    }
    __syncthreads();
    float* dst = g_Op[js] + ((size_t)(b * 32) + blockIdx.x) * 4096;
    for (int idx = tid; idx < 4096; idx += 256)
        dst[idx] = ost[(idx >> 7) * 132 + (idx & 127)];
}

// ======================= backproj: y = Wb @ sum(O) + bb + x =======================
// smem: Ot 16896 | Wbs 32768 | bbs 1024 -> 50688
#define BP_OT 0
#define BP_WB 16896
#define BP_BS 49664
#define BP_TOT 50688

__global__ __launch_bounds__(256) void backproj_kernel(
    const float* __restrict__ x, const float* __restrict__ Wb,
    const float* __restrict__ bbp, float* __restrict__ y)
{
    extern __shared__ char smb[];
    float* Ot = (float*)(smb + BP_OT);
    float* Wbs = (float*)(smb + BP_WB);
    float* bbs = (float*)(smb + BP_BS);

    const int tid = threadIdx.x;
    const int b = blockIdx.y, it = blockIdx.x, i0 = it * 128;

    for (int idx = tid; idx < CC * CPD; idx += 256) Wbs[idx] = Wb[idx];
    if (tid < CC) bbs[tid] = bbp[tid];
    {
        const size_t pofs = ((size_t)(b * 32) + it) * 4096;
        for (int idx = tid; idx < 4096; idx += 256) {
            float s = g_Op[0][pofs + idx] + g_Op[1][pofs + idx]
                    + g_Op[2][pofs + idx] + g_Op[3][pofs + idx];
            Ot[(idx >> 7) * 132 + (idx & 127)] = s;
        }
    }
    __syncthreads();

    const int i = tid & 127;
    const int half = tid >> 7;
    const size_t base = ((size_t)b * CC + half * 128) * NN + i0 + i;
    for (int cf0 = 0; cf0 < 128; cf0++) {
        const int cf = half * 128 + cf0;
        float acc = bbs[cf];
#pragma unroll
        for (int t = 0; t < 32; t += 4) {
            float4 wv = *(const float4*)&Wbs[cf * 32 + t];
            acc += wv.x * Ot[(t + 0) * 132 + i];
            acc += wv.y * Ot[(t + 1) * 132 + i];
            acc += wv.z * Ot[(t + 2) * 132 + i];
            acc += wv.w * Ot[(t + 3) * 132 + i];
        }
        const size_t off = base + (size_t)cf0 * NN;
        y[off] = acc + x[off];
    }
}

// ======================= launcher =======================
extern "C" void kernel_launch(void* const* d_in, const int* in_sizes, int n_in,
                              void* d_out, int out_size)
{
    const float* x   = (const float*)d_in[0];
    const float* Wq  = (const float*)d_in[1];
    const float* bq  = (const float*)d_in[2];
    const float* Wk  = (const float*)d_in[3];
    const float* bk  = (const float*)d_in[4];
    const float* Wv  = (const float*)d_in[5];
    const float* bv  = (const float*)d_in[6];
    const float* Wb  = (const float*)d_in[7];
    const float* bbp = (const float*)d_in[8];
    float* y = (float*)d_out;

    uint4 *dq, *dk, *dvh;
    float* dvf;
    cudaGetSymbolAddress((void**)&dq,  g_q4);
    cudaGetSymbolAddress((void**)&dk,  g_k4);
    cudaGetSymbolAddress((void**)&dvf, g_vf);
    cudaGetSymbolAddress((void**)&dvh, g_vh4);

    cudaFuncSetAttribute(proj_fused_kernel, cudaFuncAttributeMaxDynamicSharedMemorySize, 98304);
    cudaFuncSetAttribute(pass2_kernel, cudaFuncAttributeMaxDynamicSharedMemorySize, P2_TOT);
    cudaFuncSetAttribute(backproj_kernel, cudaFuncAttributeMaxDynamicSharedMemorySize, BP_TOT);

    proj_fused_kernel<<<dim3(NN / 128, BB), 128, 98304>>>(
        x, Wq, bq, Wk, bk, Wv, bv, dq, dk, dvf);
    pass1_kernel<<<dim3(NN / 128, 4, BB), 256>>>();
    scale_v_kernel<<<dim3(NN / 256, BB), 256>>>((u16*)dvh);
    pass2_kernel<<<dim3(NN / 128, 4, BB), 256, P2_TOT>>>();
    backproj_kernel<<<dim3(NN / 128, BB), 256, BP_TOT>>>(x, Wb, bbp, y);
}

// round 11
// speedup vs baseline: 6.9059x; 1.6737x over previous
#include <cuda_runtime.h>
#include <cstdint>

typedef unsigned int u32;
typedef unsigned short u16;

#define BB 8
#define CC 256
#define CPD 32
#define NN 4096
#define QPW 20   // q/k smem row pitch in words (80B)
#define LOG2E 1.4426950408889634f
#define H2_C8  0x48004800u   // fp16x2 (8, 8)
#define H2_C14 0x4B004B00u   // fp16x2 (14, 14)

// ======================= helpers =======================
__device__ __forceinline__ u32 smem_to_u32(const void* p) {
    u32 a;
    asm("{ .reg .u64 t; cvta.to.shared.u64 t, %1; cvt.u32.u64 %0, t; }" : "=r"(a) : "l"(p));
    return a;
}
__device__ __forceinline__ void mma_f16(float d[4], const u32 a[4], u32 b0, u32 b1) {
    asm volatile("mma.sync.aligned.m16n8k16.row.col.f32.f16.f16.f32 "
        "{%0,%1,%2,%3},{%4,%5,%6,%7},{%8,%9},{%0,%1,%2,%3};"
        : "+f"(d[0]), "+f"(d[1]), "+f"(d[2]), "+f"(d[3])
        : "r"(a[0]), "r"(a[1]), "r"(a[2]), "r"(a[3]), "r"(b0), "r"(b1));
}
__device__ __forceinline__ void ldsm4(u32 r[4], u32 addr) {
    asm volatile("ldmatrix.sync.aligned.m8n8.x4.shared.b16 {%0,%1,%2,%3},[%4];"
        : "=r"(r[0]), "=r"(r[1]), "=r"(r[2]), "=r"(r[3]) : "r"(addr));
}
__device__ __forceinline__ u16 f2h(float f) {
    u16 r; asm("cvt.rn.f16.f32 %0,%1;" : "=h"(r) : "f"(f)); return r;
}
__device__ __forceinline__ u32 packh(float lo, float hi) {
    u32 r; asm("cvt.rn.f16x2.f32 %0,%1,%2;" : "=r"(r) : "f"(hi), "f"(lo)); return r;
}
__device__ __forceinline__ u32 hsub2(u32 a, u32 b) {
    u32 r; asm("sub.f16x2 %0,%1,%2;" : "=r"(r) : "r"(a), "r"(b)); return r;
}
__device__ __forceinline__ u32 hmin2(u32 a, u32 b) {
    u32 r; asm("min.f16x2 %0,%1,%2;" : "=r"(r) : "r"(a), "r"(b)); return r;
}
__device__ __forceinline__ u32 hex2(u32 a) {
    u32 r; asm("ex2.approx.f16x2 %0,%1;" : "=r"(r) : "r"(a)); return r;
}
__device__ __forceinline__ float2 h2f2(u32 h) {
    float2 f;
    asm("{.reg .b16 lo,hi;\n\tmov.b32 {lo,hi},%2;\n\tcvt.f32.f16 %0,lo;\n\tcvt.f32.f16 %1,hi;}"
        : "=f"(f.x), "=f"(f.y) : "r"(h));
    return f;
}
__device__ __forceinline__ float ex2(float x) {
    float r; asm("ex2.approx.f32 %0,%1;" : "=f"(r) : "f"(x)); return r;
}

// ======================= scratch =======================
__device__ uint4 g_q4[(size_t)BB * NN * 4];          // [b][n] 32 fp16 (pre-scaled by log2e)
__device__ uint4 g_k4[(size_t)BB * NN * 4];          // [b][n] 32 fp16
__device__ float g_vf[(size_t)BB * CPD * NN];        // [b][c][n] f32 (pre-scale)
__device__ uint4 g_vh4[(size_t)BB * CPD * NN / 8];   // [b][c][n] fp16 (post scale_v: v/Z')
__device__ float g_Zp[4][BB * NN];                   // partial Z' sums (deterministic)
__device__ u32 g_Oph[4][(size_t)BB * 32 * 2048];     // partial O fp16 pairs: [b*32+it][c*64+i/2]

// ======================= proj via MMA: q/k/v =======================
// grid (32, 8), block 256. A = x tile fp16 [128n x 64c-chunk], B = W fp16 [96o x 256c].
#define PJ_WS 0          // 96 * 132 words = 50688 B
#define PJ_AS 50688      // 128 * 36 words = 18432 B
#define PJ_BIAS 69120    // 96 f32
#define PJ_TOT 69504

__global__ __launch_bounds__(256) void proj_mma_kernel(
    const float* __restrict__ x,
    const float* __restrict__ Wq, const float* __restrict__ bq,
    const float* __restrict__ Wk, const float* __restrict__ bk,
    const float* __restrict__ Wv, const float* __restrict__ bv,
    u32* __restrict__ outq, u32* __restrict__ outk, float* __restrict__ outvf)
{
    extern __shared__ char smp[];
    u32* Ws = (u32*)(smp + PJ_WS);
    u32* As = (u32*)(smp + PJ_AS);
    float* bs = (float*)(smp + PJ_BIAS);
    const u32 sbp = smem_to_u32(smp);
    const int tid = threadIdx.x, w = tid >> 5, lane = tid & 31;
    const int b = blockIdx.y, n0 = blockIdx.x * 128;

    for (int idx = tid; idx < 96 * 128; idx += 256) {
        int row = idx >> 7, c2 = idx & 127;
        const float* src = (row < 32) ? Wq : (row < 64) ? Wk : Wv;
        int o = row & 31;
        Ws[row * 132 + c2] = packh(src[o * 256 + 2 * c2], src[o * 256 + 2 * c2 + 1]);
    }
    if (tid < 96) bs[tid] = (tid < 32) ? bq[tid] : (tid < 64) ? bk[tid - 32] : bv[tid - 64];
    __syncthreads();

    float D[12][4];
#pragma unroll
    for (int ot = 0; ot < 12; ot++) {
        float b0 = bs[ot * 8 + 2 * (lane & 3)];
        float b1 = bs[ot * 8 + 2 * (lane & 3) + 1];
        D[ot][0] = b0; D[ot][1] = b1; D[ot][2] = b0; D[ot][3] = b1;
    }

    for (int kc = 0; kc < 4; kc++) {
        __syncthreads();
        for (int idx = tid; idx < 32 * 128; idx += 256) {
            int c2 = idx >> 7, n = idx & 127;
            const float* xp = x + ((size_t)(b * CC + kc * 64 + 2 * c2)) * NN + n0 + n;
            As[n * 36 + c2] = packh(xp[0], xp[NN]);
        }
        __syncthreads();
        int r = (lane & 7) + ((lane >> 3) & 1) * 8;
        u32 abase = sbp + PJ_AS + (u32)((w * 16 + r) * 144 + (lane >> 4) * 16);
#pragma unroll
        for (int k = 0; k < 4; k++) {
            u32 A[4];
            ldsm4(A, abase + k * 32);
            const int ws = lane & 3;
            const int kb = kc * 32 + k * 8;
#pragma unroll
            for (int ot = 0; ot < 12; ot++) {
                const u32* kr = Ws + (ot * 8 + (lane >> 2)) * 132 + kb;
                mma_f16(D[ot], A, kr[ws], kr[ws + 4]);
            }
        }
    }

    // epilogue
    const int nr = w * 16 + (lane >> 2);
#pragma unroll
    for (int ot = 0; ot < 4; ot++) {
        int wd = ot * 4 + (lane & 3);
        outq[((size_t)(b * NN + n0 + nr)) * 16 + wd]     = packh(D[ot][0] * LOG2E, D[ot][1] * LOG2E);
        outq[((size_t)(b * NN + n0 + nr + 8)) * 16 + wd] = packh(D[ot][2] * LOG2E, D[ot][3] * LOG2E);
    }
#pragma unroll
    for (int ot = 4; ot < 8; ot++) {
        int wd = (ot - 4) * 4 + (lane & 3);
        outk[((size_t)(b * NN + n0 + nr)) * 16 + wd]     = packh(D[ot][0], D[ot][1]);
        outk[((size_t)(b * NN + n0 + nr + 8)) * 16 + wd] = packh(D[ot][2], D[ot][3]);
    }
#pragma unroll
    for (int ot = 8; ot < 12; ot++) {
        int c = (ot - 8) * 8 + 2 * (lane & 3);
        float* v0 = outvf + ((size_t)(b * CPD + c)) * NN + n0 + nr;
        float* v1 = outvf + ((size_t)(b * CPD + c + 1)) * NN + n0 + nr;
        v0[0] = D[ot][0]; v1[0] = D[ot][1];
        v0[8] = D[ot][2]; v1[8] = D[ot][3];
    }
}

// ======================= pass 1: Z' partial sums (shifted by -8) =======================
// grid (32 j-tiles, 4 i-splits, 8 b), block 256
__global__ __launch_bounds__(256) void pass1_kernel()
{
    __shared__ __align__(16) u32 Qs[128 * QPW];
    __shared__ __align__(16) u32 Ks[128 * QPW];
    const int tid = threadIdx.x, w = tid >> 5, lane = tid & 31;
    const int b = blockIdx.z, j0 = blockIdx.x * 128, it0 = blockIdx.y * 8;

    for (int idx = tid; idx < 512; idx += 256) {
        int row = idx >> 2, q = idx & 3;
        uint4 v = g_q4[(size_t)(b * NN + j0 + row) * 4 + q];
        *(uint4*)((char*)Qs + row * 80 + q * 16) = v;
    }
    __syncthreads();

    u32 A[2][4];
    {
        int r = (lane & 7) + ((lane >> 3) & 1) * 8;
        u32 base = smem_to_u32(Qs) + (u32)((w * 16 + r) * 80 + (lane >> 4) * 16);
        ldsm4(A[0], base); ldsm4(A[1], base + 32);
    }

    float z0 = 0.f, z1 = 0.f;
    for (int it = it0; it < it0 + 8; it++) {
        __syncthreads();
        for (int idx = tid; idx < 512; idx += 256) {
            int row = idx >> 2, q = idx & 3;
            uint4 v = g_k4[(size_t)(b * NN + it * 128 + row) * 4 + q];
            *(uint4*)((char*)Ks + row * 80 + q * 16) = v;
        }
        __syncthreads();

#pragma unroll
        for (int nf = 0; nf < 16; nf++) {
            float d[4] = {0.f, 0.f, 0.f, 0.f};
            const u32* kr = Ks + (nf * 8 + (lane >> 2)) * QPW;
            const int ws = lane & 3;
            mma_f16(d, A[0], kr[ws], kr[ws + 4]);
            mma_f16(d, A[1], kr[ws + 8], kr[ws + 12]);
            u32 e0 = hex2(hmin2(hsub2(packh(d[0], d[1]), H2_C8), H2_C14));
            u32 e1 = hex2(hmin2(hsub2(packh(d[2], d[3]), H2_C8), H2_C14));
            float2 f0 = h2f2(e0), f1 = h2f2(e1);
            z0 += f0.x + f0.y;
            z1 += f1.x + f1.y;
        }
    }

    z0 += __shfl_xor_sync(0xffffffff, z0, 1);
    z0 += __shfl_xor_sync(0xffffffff, z0, 2);
    z1 += __shfl_xor_sync(0xffffffff, z1, 1);
    z1 += __shfl_xor_sync(0xffffffff, z1, 2);
    if ((lane & 3) == 0) {
        int j = j0 + w * 16 + (lane >> 2);
        g_Zp[blockIdx.y][b * NN + j]     = z0;
        g_Zp[blockIdx.y][b * NN + j + 8] = z1;
    }
}

// ======================= scale_v: V_fp16 = V_f32 / Z' =======================
__global__ __launch_bounds__(256) void scale_v_kernel(u16* __restrict__ vh)
{
    const int n = blockIdx.x * 256 + threadIdx.x;
    const int b = blockIdx.y;
    const int o = b * NN + n;
    float Z = g_Zp[0][o] + g_Zp[1][o] + g_Zp[2][o] + g_Zp[3][o];
    float iZ = 1.0f / Z;
#pragma unroll 4
    for (int c = 0; c < CPD; c++) {
        size_t off = ((size_t)(b * CPD + c)) * NN + n;
        vh[off] = f2h(g_vf[off] * iZ);
    }
}

// ======================= pass 2: S + exp + PV, partial O (fp16) =======================
#define P2_KS 0
#define P2_QS 10240
#define P2_VS 20480
#define P2_TOT 29184

__global__ __launch_bounds__(256) void pass2_kernel()
{
    extern __shared__ char sm2[];
    u32* Ks = (u32*)(sm2 + P2_KS);
    u32* Qs = (u32*)(sm2 + P2_QS);
    u32* Vs = (u32*)(sm2 + P2_VS);
    float* ost = (float*)sm2;
    const u32 sb2 = smem_to_u32(sm2);

    const int tid = threadIdx.x, w = tid >> 5, lane = tid & 31;
    const int b = blockIdx.z, i0 = blockIdx.x * 128, js = blockIdx.y;

    for (int idx = tid; idx < 512; idx += 256) {
        int row = idx >> 2, q = idx & 3;
        uint4 v = g_k4[(size_t)(b * NN + i0 + row) * 4 + q];
        *(uint4*)((char*)Ks + row * 80 + q * 16) = v;
    }
    __syncthreads();

    u32 KA[2][4];
    {
        int r = (lane & 7) + ((lane >> 3) & 1) * 8;
        u32 base = sb2 + P2_KS + (u32)((w * 16 + r) * 80 + (lane >> 4) * 16);
        ldsm4(KA[0], base); ldsm4(KA[1], base + 32);
    }

    float dO[4][4];
#pragma unroll
    for (int cf = 0; cf < 4; cf++)
#pragma unroll
        for (int r = 0; r < 4; r++) dO[cf][r] = 0.f;

    for (int jt = js * 8; jt < js * 8 + 8; jt++) {
        __syncthreads();
        const int jb = jt * 128;
        for (int idx = tid; idx < 512; idx += 256) {
            int row = idx >> 2, q = idx & 3;
            uint4 v = g_q4[(size_t)(b * NN + jb + row) * 4 + q];
            *(uint4*)((char*)Qs + row * 80 + q * 16) = v;
        }
        for (int idx = tid; idx < 512; idx += 256) {
            int row = idx >> 4, q = idx & 15;
            uint4 v = g_vh4[(size_t)(b * CPD + row) * (NN / 8) + (jb >> 3) + q];
            *(uint4*)((char*)Vs + row * 272 + q * 16) = v;
        }
        __syncthreads();

#pragma unroll
        for (int jp = 0; jp < 8; jp++) {
            float d0[4] = {0.f, 0.f, 0.f, 0.f}, d1[4] = {0.f, 0.f, 0.f, 0.f};
            const int ws = lane & 3;
            {
                const u32* qr = Qs + (jp * 16 + (lane >> 2)) * QPW;
                mma_f16(d0, KA[0], qr[ws], qr[ws + 4]);
                mma_f16(d0, KA[1], qr[ws + 8], qr[ws + 12]);
            }
            {
                const u32* qr = Qs + (jp * 16 + 8 + (lane >> 2)) * QPW;
                mma_f16(d1, KA[0], qr[ws], qr[ws + 4]);
                mma_f16(d1, KA[1], qr[ws + 8], qr[ws + 12]);
            }
            // P' = exp2(S' - 8), fp16x2 MUFU, clamp at 14
            u32 aH[4];
            aH[0] = hex2(hmin2(hsub2(packh(d0[0], d0[1]), H2_C8), H2_C14));
            aH[1] = hex2(hmin2(hsub2(packh(d0[2], d0[3]), H2_C8), H2_C14));
            aH[2] = hex2(hmin2(hsub2(packh(d1[0], d1[1]), H2_C8), H2_C14));
            aH[3] = hex2(hmin2(hsub2(packh(d1[2], d1[3]), H2_C8), H2_C14));
            const int ws2 = jp * 8 + (lane & 3);
#pragma unroll
            for (int cf = 0; cf < 4; cf++) {
                const u32* vh = Vs + (cf * 8 + (lane >> 2)) * 68;
                mma_f16(dO[cf], aH, vh[ws2], vh[ws2 + 4]);
            }
        }
    }

    // stage dO -> ost[c][i], then packed fp16 partial store
    __syncthreads();
#pragma unroll
    for (int cf = 0; cf < 4; cf++) {
        int c = cf * 8 + 2 * (lane & 3);
        int ig = w * 16 + (lane >> 2);
        ost[c * 132 + ig]           = dO[cf][0];
        ost[(c + 1) * 132 + ig]     = dO[cf][1];
        ost[c * 132 + ig + 8]       = dO[cf][2];
        ost[(c + 1) * 132 + ig + 8] = dO[cf][3];
    }
    __syncthreads();
    u32* dst = g_Oph[js] + ((size_t)(b * 32) + blockIdx.x) * 2048;
    for (int idx = tid; idx < 2048; idx += 256) {
        int c = idx >> 6, ip = idx & 63;
        dst[idx] = packh(ost[c * 132 + 2 * ip], ost[c * 132 + 2 * ip + 1]);
    }
}

// ======================= backproj: y = Wb @ sum(O) + bb + x =======================
#define BP_OT 0
#define BP_WB 16896
#define BP_BS 49664
#define BP_TOT 50688

__global__ __launch_bounds__(256) void backproj_kernel(
    const float* __restrict__ x, const float* __restrict__ Wb,
    const float* __restrict__ bbp, float* __restrict__ y)
{
    extern __shared__ char smb[];
    float* Ot = (float*)(smb + BP_OT);
    float* Wbs = (float*)(smb + BP_WB);
    float* bbs = (float*)(smb + BP_BS);

    const int tid = threadIdx.x;
    const int b = blockIdx.y, it = blockIdx.x, i0 = it * 128;

    for (int idx = tid; idx < CC * CPD; idx += 256) Wbs[idx] = Wb[idx];
    if (tid < CC) bbs[tid] = bbp[tid];
    {
        const size_t pofs = ((size_t)(b * 32) + it) * 2048;
        for (int idx = tid; idx < 2048; idx += 256) {
            float2 s0 = h2f2(g_Oph[0][pofs + idx]);
            float2 s1 = h2f2(g_Oph[1][pofs + idx]);
            float2 s2 = h2f2(g_Oph[2][pofs + idx]);
            float2 s3 = h2f2(g_Oph[3][pofs + idx]);
            int c = idx >> 6, ip = idx & 63;
            Ot[c * 132 + 2 * ip]     = s0.x + s1.x + s2.x + s3.x;
            Ot[c * 132 + 2 * ip + 1] = s0.y + s1.y + s2.y + s3.y;
        }
    }
    __syncthreads();

    const int i = tid & 127;
    const int half = tid >> 7;
    const size_t base = ((size_t)b * CC + half * 128) * NN + i0 + i;
    for (int cf0 = 0; cf0 < 128; cf0++) {
        const int cf = half * 128 + cf0;
        float acc = bbs[cf];
#pragma unroll
        for (int t = 0; t < 32; t += 4) {
            float4 wv = *(const float4*)&Wbs[cf * 32 + t];
            acc += wv.x * Ot[(t + 0) * 132 + i];
            acc += wv.y * Ot[(t + 1) * 132 + i];
            acc += wv.z * Ot[(t + 2) * 132 + i];
            acc += wv.w * Ot[(t + 3) * 132 + i];
        }
        const size_t off = base + (size_t)cf0 * NN;
        y[off] = acc + x[off];
    }
}

// ======================= launcher =======================
extern "C" void kernel_launch(void* const* d_in, const int* in_sizes, int n_in,
                              void* d_out, int out_size)
{
    const float* x   = (const float*)d_in[0];
    const float* Wq  = (const float*)d_in[1];
    const float* bq  = (const float*)d_in[2];
    const float* Wk  = (const float*)d_in[3];
    const float* bk  = (const float*)d_in[4];
    const float* Wv  = (const float*)d_in[5];
    const float* bv  = (const float*)d_in[6];
    const float* Wb  = (const float*)d_in[7];
    const float* bbp = (const float*)d_in[8];
    float* y = (float*)d_out;

    uint4 *dq, *dk, *dvh;
    float* dvf;
    cudaGetSymbolAddress((void**)&dq,  g_q4);
    cudaGetSymbolAddress((void**)&dk,  g_k4);
    cudaGetSymbolAddress((void**)&dvf, g_vf);
    cudaGetSymbolAddress((void**)&dvh, g_vh4);

    cudaFuncSetAttribute(proj_mma_kernel, cudaFuncAttributeMaxDynamicSharedMemorySize, PJ_TOT);
    cudaFuncSetAttribute(pass2_kernel, cudaFuncAttributeMaxDynamicSharedMemorySize, P2_TOT);
    cudaFuncSetAttribute(backproj_kernel, cudaFuncAttributeMaxDynamicSharedMemorySize, BP_TOT);

    proj_mma_kernel<<<dim3(NN / 128, BB), 256, PJ_TOT>>>(
        x, Wq, bq, Wk, bk, Wv, bv, (u32*)dq, (u32*)dk, dvf);
    pass1_kernel<<<dim3(NN / 128, 4, BB), 256>>>();
    scale_v_kernel<<<dim3(NN / 256, BB), 256>>>((u16*)dvh);
    pass2_kernel<<<dim3(NN / 128, 4, BB), 256, P2_TOT>>>();
    backproj_kernel<<<dim3(NN / 128, BB), 256, BP_TOT>>>(x, Wb, bbp, y);
}